// round 12
// baseline (speedup 1.0000x reference)
#include <cuda_runtime.h>
#include <cuda_fp16.h>
#include <cstdint>

#define BB   64
#define SS   4096
#define HH   256
#define FF   512      // 2*H
#define OUTD 24
#define NCHUNK 16     // s-chunks for context partials

// ---------------- scratch (static device globals; no allocs) ----------------
__device__ __align__(16) float g_qWh[BB*HH];      // hidden_q @ W_h + attn_b
__device__ __align__(16) float g_embT[BB*HH];     // gathered emb_temp
__device__ __align__(16) float g_scores[BB*SS];   // attn weights (post-softmax)
__device__ __align__(16) float g_spart[2*BB*SS];  // score partials per n-half
__device__ __align__(16) float g_part[NCHUNK*BB*FF]; // context partial sums
__device__ __align__(16) __half g_Wh[HH*FF];      // W_e^T fp16 [n=256][k=512]

// ---------------- helpers ----------------
__device__ __forceinline__ uint32_t smem_u32(const void* p) {
    uint32_t a;
    asm("{ .reg .u64 t; cvta.to.shared.u64 t, %1; cvt.u32.u64 %0, t; }"
        : "=r"(a) : "l"(p));
    return a;
}
__device__ __forceinline__ void cp_async16(void* sm, const void* g) {
    unsigned s = (unsigned)__cvta_generic_to_shared(sm);
    asm volatile("cp.async.cg.shared.global [%0], [%1], 16;" :: "r"(s), "l"(g));
}
#define CP_COMMIT() asm volatile("cp.async.commit_group;")
#define CP_WAIT0()  asm volatile("cp.async.wait_group 0;")

__device__ __forceinline__ void ldsm_x4(uint32_t* r, uint32_t addr) {
    asm volatile("ldmatrix.sync.aligned.m8n8.x4.shared.b16 {%0,%1,%2,%3}, [%4];"
        : "=r"(r[0]), "=r"(r[1]), "=r"(r[2]), "=r"(r[3]) : "r"(addr));
}
__device__ __forceinline__ void mma_fp16(float* c, const uint32_t* a, const uint32_t* b) {
    asm volatile("mma.sync.aligned.m16n8k16.row.col.f32.f16.f16.f32 "
        "{%0,%1,%2,%3}, {%4,%5,%6,%7}, {%8,%9}, {%0,%1,%2,%3};"
        : "+f"(c[0]), "+f"(c[1]), "+f"(c[2]), "+f"(c[3])
        : "r"(a[0]), "r"(a[1]), "r"(a[2]), "r"(a[3]), "r"(b[0]), "r"(b[1]));
}
// swizzles: 16B chunk c of row r; XOR low-3 bits of chunk with (r&7)
__device__ __forceinline__ uint32_t sw256(int r, int c) {   // 256B rows (A, c 0..15)
    return (uint32_t)(r*256 + ((c ^ (r & 7)) << 4));
}
__device__ __forceinline__ uint32_t sw1024(int r, int c) {  // 1024B rows (B, c 0..63)
    return (uint32_t)(r*1024 + ((c ^ (r & 7)) << 4));
}
__device__ __forceinline__ float sigmoidf_(float x) { return 1.0f / (1.0f + expf(-x)); }

// ---------------- kernel 1: gathers + qWh = emb_ctxt[idx] @ W_h + attn_b ----
__global__ void setup_kernel(const int* __restrict__ fc, const int* __restrict__ ft,
                             const float* __restrict__ emb_c, const float* __restrict__ emb_t,
                             const float* __restrict__ attn_W, const float* __restrict__ attn_b)
{
    __shared__ float q[HH];
    int b = blockIdx.x, tid = threadIdx.x;
    int ci = fc[b], ti = ft[b];
    q[tid] = emb_c[ci*HH + tid];
    g_embT[b*HH + tid] = emb_t[ti*HH + tid];
    __syncthreads();
    float acc = attn_b[tid];
#pragma unroll 8
    for (int k = 0; k < HH; k++) acc += q[k] * attn_W[k*HH + tid];
    g_qWh[b*HH + tid] = acc;
}

// ---------------- kernel 1b: W_e transpose + fp16 convert ----------------
__global__ void prep_W(const float* __restrict__ attn_W)
{
    const float* We = attn_W + HH*HH;                  // [k=512][n=256]
    int idx = blockIdx.x * 256 + threadIdx.x;          // 131072
    int k = idx >> 8, n = idx & 255;
    g_Wh[n*FF + k] = __float2half_rn(We[k*HH + n]);
}

// ---------------- kernel 2: fp16 mma.sync scores GEMM, B smem-resident ----
// Grid (2 n-halves, 64 b) = 128 persistent-ish CTAs, 512 threads (16 warps,
// 4m x 4n, warp tile 32x32). Each CTA: loads its B half [128n x 512k] fp16
// (128KB) into smem ONCE, then loops 32 s-tiles x 4 k-chunks (chunk=128k)
// with a double-buffered A stage (LDG fp32 E -> cvt fp16 -> STS).
#define A0OFF   0
#define A1OFF   32768
#define B_OFF   65536               // 128KB resident B
#define SM_QW   196608
#define SM_V    197120
#define SM_RED  197632
#define SMEM_SC 199680

__global__ void __launch_bounds__(512, 1)
scores_mma(const float* __restrict__ E, const float* __restrict__ v)
{
    extern __shared__ char sm[];
    const uint32_t smb = smem_u32(sm);
    const int tid  = threadIdx.x;
    const int lane = tid & 31, warp = tid >> 5;
    const int wm = warp >> 2, wn = warp & 3;       // 4 x 4 warp grid
    const int half = blockIdx.x;
    const int b    = blockIdx.y;
    const int nbase = half * 128;

    float* sq = (float*)(sm + SM_QW);
    float* sv = (float*)(sm + SM_V);
    if (tid < 128) {
        sq[tid] = g_qWh[b*HH + nbase + tid];
        sv[tid] = v[nbase + tid];
    }

    // ---- B resident load: 128 rows x 64 chunks = 8192 cp.async, once ----
#pragma unroll
    for (int j = 0; j < 16; j++) {
        int idx = tid + 512*j;
        int br = idx >> 6, bc = idx & 63;
        cp_async16(sm + B_OFF + sw1024(br, bc),
                   g_Wh + (long)(nbase + br)*FF + bc*8);
    }
    CP_COMMIT();

    // A producer mapping: row0 = tid>>2 (0..127), seg = tid&3 (32 k each)
    const int seg  = tid & 3;
    const int row0 = tid >> 2;
    const uint32_t dA[4] = { sw256(row0, seg*4 + 0), sw256(row0, seg*4 + 1),
                             sw256(row0, seg*4 + 2), sw256(row0, seg*4 + 3) };

    // store one 16-float half (h=0/1) converted to fp16 into stage stp
#define A_HALF_STS(stp, h, f0, f1, f2, f3)                                       \
    do {                                                                         \
        __half2 h0 = __floats2half2_rn((f0).x, (f0).y);                          \
        __half2 h1 = __floats2half2_rn((f0).z, (f0).w);                          \
        __half2 h2 = __floats2half2_rn((f1).x, (f1).y);                          \
        __half2 h3 = __floats2half2_rn((f1).z, (f1).w);                          \
        __half2 h4 = __floats2half2_rn((f2).x, (f2).y);                          \
        __half2 h5 = __floats2half2_rn((f2).z, (f2).w);                          \
        __half2 h6 = __floats2half2_rn((f3).x, (f3).y);                          \
        __half2 h7 = __floats2half2_rn((f3).z, (f3).w);                          \
        *(uint4*)((stp) + dA[(h)*2 + 0]) = make_uint4(                           \
            *(uint32_t*)&h0, *(uint32_t*)&h1, *(uint32_t*)&h2, *(uint32_t*)&h3); \
        *(uint4*)((stp) + dA[(h)*2 + 1]) = make_uint4(                           \
            *(uint32_t*)&h4, *(uint32_t*)&h5, *(uint32_t*)&h6, *(uint32_t*)&h7); \
    } while (0)

    // global A pointer for linear chunk c (tile = c>>2, kc = c&3)
#define A_PTR(c) (E + ((long)(b*SS) + ((c) >> 2)*128 + row0)*FF + ((c) & 3)*128 + seg*32)

    float acc[2][4][4];
#pragma unroll
    for (int mt = 0; mt < 2; mt++)
#pragma unroll
        for (int nt = 0; nt < 4; nt++)
#pragma unroll
            for (int e = 0; e < 4; e++) acc[mt][nt][e] = 0.0f;

    // ---- prologue: produce A chunk 0 into stage 0 ----
    {
        const float* Ap = A_PTR(0);
        float4 f0 = *(const float4*)(Ap);
        float4 f1 = *(const float4*)(Ap + 4);
        float4 f2 = *(const float4*)(Ap + 8);
        float4 f3 = *(const float4*)(Ap + 12);
        A_HALF_STS(sm + A0OFF, 0, f0, f1, f2, f3);
        f0 = *(const float4*)(Ap + 16);
        f1 = *(const float4*)(Ap + 20);
        f2 = *(const float4*)(Ap + 24);
        f3 = *(const float4*)(Ap + 28);
        A_HALF_STS(sm + A0OFF, 1, f0, f1, f2, f3);
        CP_WAIT0();            // drains B resident load too
        __syncthreads();
    }

    float* red = (float*)(sm + SM_RED);   // [128 rows][4 n-warp groups]

    for (int c = 0; c < 128; c++) {
        const int cur = c & 1;
        const uint32_t stA = smb + (cur ? A1OFF : A0OFF);
        char* stn = sm + (cur ? A0OFF : A1OFF);
        const int kc = c & 3;
        const bool pf = (c < 127);

        // prefetch half0 of A(c+1)
        float4 f0, f1, f2, f3;
        const float* Apn = pf ? A_PTR(c + 1) : (const float*)0;
        if (pf) {
            f0 = *(const float4*)(Apn);
            f1 = *(const float4*)(Apn + 4);
            f2 = *(const float4*)(Apn + 8);
            f3 = *(const float4*)(Apn + 12);
        }

        // ---- MMA ks 0..3 ----
#pragma unroll
        for (int ks = 0; ks < 4; ks++) {
            uint32_t af[2][4];
#pragma unroll
            for (int mt = 0; mt < 2; mt++) {
                int r = wm*32 + mt*16 + (lane & 15);
                ldsm_x4(af[mt], stA + sw256(r, ks*2 + (lane >> 4)));
            }
#pragma unroll
            for (int np = 0; np < 2; np++) {
                int nr = wn*32 + np*16 + ((lane >> 4) << 3) + (lane & 7);
                int cc = (kc*8 + ks)*2 + ((lane >> 3) & 1);
                uint32_t r4[4];
                ldsm_x4(r4, smb + B_OFF + sw1024(nr, cc));
                uint32_t b0[2] = { r4[0], r4[1] };
                uint32_t b1[2] = { r4[2], r4[3] };
#pragma unroll
                for (int mt = 0; mt < 2; mt++) {
                    mma_fp16(acc[mt][np*2],     af[mt], b0);
                    mma_fp16(acc[mt][np*2 + 1], af[mt], b1);
                }
            }
        }

        // store half0, prefetch half1
        if (pf) {
            A_HALF_STS(stn, 0, f0, f1, f2, f3);
            f0 = *(const float4*)(Apn + 16);
            f1 = *(const float4*)(Apn + 20);
            f2 = *(const float4*)(Apn + 24);
            f3 = *(const float4*)(Apn + 28);
        }

        // ---- MMA ks 4..7 ----
#pragma unroll
        for (int ks = 4; ks < 8; ks++) {
            uint32_t af[2][4];
#pragma unroll
            for (int mt = 0; mt < 2; mt++) {
                int r = wm*32 + mt*16 + (lane & 15);
                ldsm_x4(af[mt], stA + sw256(r, ks*2 + (lane >> 4)));
            }
#pragma unroll
            for (int np = 0; np < 2; np++) {
                int nr = wn*32 + np*16 + ((lane >> 4) << 3) + (lane & 7);
                int cc = (kc*8 + ks)*2 + ((lane >> 3) & 1);
                uint32_t r4[4];
                ldsm_x4(r4, smb + B_OFF + sw1024(nr, cc));
                uint32_t b0[2] = { r4[0], r4[1] };
                uint32_t b1[2] = { r4[2], r4[3] };
#pragma unroll
                for (int mt = 0; mt < 2; mt++) {
                    mma_fp16(acc[mt][np*2],     af[mt], b0);
                    mma_fp16(acc[mt][np*2 + 1], af[mt], b1);
                }
            }
        }

        if (pf) A_HALF_STS(stn, 1, f0, f1, f2, f3);
        __syncthreads();   // publish stage c+1; acc of tile complete if kc==3

        // ---- per-tile epilogue: +qWh, tanh, dot v over this n-half ----
        if (kc == 3) {
            const int ss = (c >> 2) * 128;
#pragma unroll
            for (int mt = 0; mt < 2; mt++) {
                float pA = 0.0f, pB = 0.0f;
#pragma unroll
                for (int nt = 0; nt < 4; nt++) {
                    int h0 = wn*32 + nt*8 + (lane & 3)*2;
                    float q0 = sq[h0], q1 = sq[h0 + 1];
                    float v0 = sv[h0], v1 = sv[h0 + 1];
                    pA += v0*tanhf(acc[mt][nt][0] + q0) + v1*tanhf(acc[mt][nt][1] + q1);
                    pB += v0*tanhf(acc[mt][nt][2] + q0) + v1*tanhf(acc[mt][nt][3] + q1);
                }
                pA += __shfl_xor_sync(0xffffffffu, pA, 1);
                pA += __shfl_xor_sync(0xffffffffu, pA, 2);
                pB += __shfl_xor_sync(0xffffffffu, pB, 1);
                pB += __shfl_xor_sync(0xffffffffu, pB, 2);
                if ((lane & 3) == 0) {
                    int r = wm*32 + mt*16 + (lane >> 2);
                    red[r*4 + wn]       = pA;
                    red[(r + 8)*4 + wn] = pB;
                }
            }
            __syncthreads();
            if (tid < 128) {
                float s = red[tid*4] + red[tid*4+1] + red[tid*4+2] + red[tid*4+3];
                g_spart[((long)half*BB + b)*SS + ss + tid] = s;
            }
            // reset accumulators for next tile
#pragma unroll
            for (int mt = 0; mt < 2; mt++)
#pragma unroll
                for (int nt = 0; nt < 4; nt++)
#pragma unroll
                    for (int e = 0; e < 4; e++) acc[mt][nt][e] = 0.0f;
            __syncthreads();
        }
    }
}

// ---------------- kernel 3: sum halves + softmax -> g_scores ----------------
__global__ void softmax_kernel()
{
    __shared__ float red[32];
    const int b = blockIdx.x, tid = threadIdx.x;
    const float* p0 = g_spart + (long)b*SS;
    const float* p1 = g_spart + (long)(BB + b)*SS;
    float4 a0 = *(const float4*)(p0 + tid*4);
    float4 a1 = *(const float4*)(p1 + tid*4);
    float4 xv = make_float4(a0.x + a1.x, a0.y + a1.y, a0.z + a1.z, a0.w + a1.w);
    const unsigned lane = tid & 31, w = tid >> 5;

    float mx = fmaxf(fmaxf(xv.x, xv.y), fmaxf(xv.z, xv.w));
#pragma unroll
    for (int o = 16; o; o >>= 1) mx = fmaxf(mx, __shfl_xor_sync(0xffffffffu, mx, o));
    if (!lane) red[w] = mx;
    __syncthreads();
    if (tid < 32) {
        float t = red[tid];
#pragma unroll
        for (int o = 16; o; o >>= 1) t = fmaxf(t, __shfl_xor_sync(0xffffffffu, t, o));
        if (!tid) red[0] = t;
    }
    __syncthreads();
    const float mm = red[0];
    __syncthreads();

    float4 ev = make_float4(expf(xv.x - mm), expf(xv.y - mm),
                            expf(xv.z - mm), expf(xv.w - mm));
    float s = ev.x + ev.y + ev.z + ev.w;
#pragma unroll
    for (int o = 16; o; o >>= 1) s += __shfl_xor_sync(0xffffffffu, s, o);
    if (!lane) red[w] = s;
    __syncthreads();
    if (tid < 32) {
        float t = red[tid];
#pragma unroll
        for (int o = 16; o; o >>= 1) t += __shfl_xor_sync(0xffffffffu, t, o);
        if (!tid) red[0] = t;
    }
    __syncthreads();
    const float inv = 1.0f / red[0];
    ev.x *= inv; ev.y *= inv; ev.z *= inv; ev.w *= inv;
    *(float4*)(g_scores + b*SS + tid*4) = ev;
}

// ---------------- kernel 4: context partials: part[c][b][f] ----------------
__global__ void ctx_kernel(const float* __restrict__ E)
{
    __shared__ float sa[SS / NCHUNK];
    const int c = blockIdx.x, b = blockIdx.y, tid = threadIdx.x; // 128 threads
    const int s0 = c * (SS / NCHUNK);
    sa[tid]       = g_scores[b*SS + s0 + tid];
    sa[tid + 128] = g_scores[b*SS + s0 + tid + 128];
    __syncthreads();

    float4 acc = make_float4(0.f, 0.f, 0.f, 0.f);
    const float* base = E + (long)(b*SS + s0) * FF + tid*4;
#pragma unroll 8
    for (int s = 0; s < SS / NCHUNK; s++) {
        const float a = sa[s];
        const float4 e = *(const float4*)(base + (long)s * FF);
        acc.x += a*e.x; acc.y += a*e.y; acc.z += a*e.z; acc.w += a*e.w;
    }
    *(float4*)(&g_part[(long)(c*BB + b)*FF + tid*4]) = acc;
}

// ---------------- kernel 5: reduce + GRU + output projection ----------------
__global__ void gru_kernel(const float* __restrict__ w_ih, const float* __restrict__ b_ih,
                           const float* __restrict__ b_hh, const float* __restrict__ out_W,
                           const float* __restrict__ out_b, float* __restrict__ out,
                           int out_size)
{
    __shared__ float x[3*HH];
    __shared__ float g[3*HH];
    __shared__ float h[HH];
    const int b = blockIdx.x, tid = threadIdx.x; // 256 threads

#pragma unroll
    for (int r = 0; r < 2; r++) {
        const int f = tid + r*256;
        float acc = 0.0f;
#pragma unroll
        for (int c = 0; c < NCHUNK; c++) acc += g_part[(long)(c*BB + b)*FF + f];
        x[HH + f] = acc;
    }
    x[tid] = g_embT[b*HH + tid];
    __syncthreads();

#pragma unroll
    for (int r = 0; r < 3; r++) {
        const int jj = tid + r*256;
        float acc = b_ih[jj];
#pragma unroll 8
        for (int k = 0; k < 3*HH; k++) acc += x[k] * w_ih[k*(3*HH) + jj];
        g[jj] = acc;
    }
    __syncthreads();

    {
        const int j = tid;
        const float rg = sigmoidf_(g[j]        + b_hh[j]);
        const float zg = sigmoidf_(g[HH + j]   + b_hh[HH + j]);
        const float ng = tanhf   (g[2*HH + j]  + rg * b_hh[2*HH + j]);
        const float hv = (1.0f - zg) * ng;
        h[j] = hv;
        const int ho = BB*OUTD + b*HH + j;
        if (ho < out_size) out[ho] = hv;
    }
    __syncthreads();

    if (tid < OUTD) {
        float acc = out_b[tid];
#pragma unroll 8
        for (int k = 0; k < HH; k++) acc += h[k] * out_W[k*OUTD + tid];
        out[b*OUTD + tid] = acc;
    }
}

// ---------------- launch ----------------
extern "C" void kernel_launch(void* const* d_in, const int* in_sizes, int n_in,
                              void* d_out, int out_size)
{
    const int*   fc     = (const int*)  d_in[0];   // fut_ctxt (B,1)
    const int*   ft     = (const int*)  d_in[1];   // fut_temp (B,1)
    const float* E      = (const float*)d_in[2];   // encoder_outputs (B,S,2H)
    const float* emb_c  = (const float*)d_in[3];   // emb_ctxt (1000,H)
    const float* emb_t  = (const float*)d_in[4];   // emb_temp (1000,H)
    const float* attn_W = (const float*)d_in[5];   // (3H,H)
    const float* attn_b = (const float*)d_in[6];   // (H,)
    const float* v      = (const float*)d_in[7];   // (H,)
    const float* w_ih   = (const float*)d_in[8];   // (3H,3H)
    // d_in[9] = w_hh: unused since h0 == 0 (gh = b_hh exactly)
    const float* b_ih   = (const float*)d_in[10];  // (3H,)
    const float* b_hh   = (const float*)d_in[11];  // (3H,)
    const float* out_W  = (const float*)d_in[12];  // (H,OUT)
    const float* out_b  = (const float*)d_in[13];  // (OUT,)
    float* out = (float*)d_out;

    cudaFuncSetAttribute(scores_mma, cudaFuncAttributeMaxDynamicSharedMemorySize,
                         SMEM_SC);

    setup_kernel<<<BB, HH>>>(fc, ft, emb_c, emb_t, attn_W, attn_b);
    prep_W<<<512, 256>>>(attn_W);
    scores_mma<<<dim3(2, BB), 512, SMEM_SC>>>(E, v);
    softmax_kernel<<<BB, 1024>>>();
    ctx_kernel<<<dim3(NCHUNK, BB), 128>>>(E);
    gru_kernel<<<BB, 256>>>(w_ih, b_ih, b_hh, out_W, out_b, out, out_size);
}

// round 13
// speedup vs baseline: 1.6675x; 1.6675x over previous
#include <cuda_runtime.h>
#include <cuda_fp16.h>
#include <cstdint>

#define BB   64
#define SS   4096
#define HH   256
#define FF   512      // 2*H
#define OUTD 24
#define NTILE 64      // s-tiles per batch (64 rows each)

// ---------------- scratch (static device globals; no allocs) ----------------
__device__ __align__(16) float g_qWh[BB*HH];      // hidden_q @ W_h + attn_b
__device__ __align__(16) float g_embT[BB*HH];     // gathered emb_temp
__device__ __align__(16) float g_part[NTILE*BB*FF]; // ctx partials per tile
__device__ __align__(16) float2 g_ms[BB*NTILE];   // (local max, local expsum)
__device__ __align__(16) __half g_Wh[HH*FF];      // W_e^T fp16 [n=256][k=512]

// ---------------- helpers ----------------
__device__ __forceinline__ uint32_t smem_u32(const void* p) {
    uint32_t a;
    asm("{ .reg .u64 t; cvta.to.shared.u64 t, %1; cvt.u32.u64 %0, t; }"
        : "=r"(a) : "l"(p));
    return a;
}
__device__ __forceinline__ void cp_async16(void* sm, const void* g) {
    unsigned s = (unsigned)__cvta_generic_to_shared(sm);
    asm volatile("cp.async.cg.shared.global [%0], [%1], 16;" :: "r"(s), "l"(g));
}
#define CP_COMMIT() asm volatile("cp.async.commit_group;")
#define CP_WAIT0()  asm volatile("cp.async.wait_group 0;")

__device__ __forceinline__ void ldsm_x4(uint32_t* r, uint32_t addr) {
    asm volatile("ldmatrix.sync.aligned.m8n8.x4.shared.b16 {%0,%1,%2,%3}, [%4];"
        : "=r"(r[0]), "=r"(r[1]), "=r"(r[2]), "=r"(r[3]) : "r"(addr));
}
__device__ __forceinline__ void mma_fp16(float* c, const uint32_t* a, const uint32_t* b) {
    asm volatile("mma.sync.aligned.m16n8k16.row.col.f32.f16.f16.f32 "
        "{%0,%1,%2,%3}, {%4,%5,%6,%7}, {%8,%9}, {%0,%1,%2,%3};"
        : "+f"(c[0]), "+f"(c[1]), "+f"(c[2]), "+f"(c[3])
        : "r"(a[0]), "r"(a[1]), "r"(a[2]), "r"(a[3]), "r"(b[0]), "r"(b[1]));
}
// 128B-row swizzle: 16B chunk c (0..7) of row r
__device__ __forceinline__ uint32_t sw128(int r, int c) {
    return (uint32_t)(r*128 + ((c ^ (r & 7)) << 4));
}
__device__ __forceinline__ float sigmoidf_(float x) { return 1.0f / (1.0f + expf(-x)); }

// ---------------- kernel 1: gathers + qWh = emb_ctxt[idx] @ W_h + attn_b ----
__global__ void setup_kernel(const int* __restrict__ fc, const int* __restrict__ ft,
                             const float* __restrict__ emb_c, const float* __restrict__ emb_t,
                             const float* __restrict__ attn_W, const float* __restrict__ attn_b)
{
    __shared__ float q[HH];
    int b = blockIdx.x, tid = threadIdx.x;
    int ci = fc[b], ti = ft[b];
    q[tid] = emb_c[ci*HH + tid];
    g_embT[b*HH + tid] = emb_t[ti*HH + tid];
    __syncthreads();
    float acc = attn_b[tid];
#pragma unroll 8
    for (int k = 0; k < HH; k++) acc += q[k] * attn_W[k*HH + tid];
    g_qWh[b*HH + tid] = acc;
}

// ---------------- kernel 1b: W_e transpose + fp16 convert ----------------
__global__ void prep_W(const float* __restrict__ attn_W)
{
    const float* We = attn_W + HH*HH;                  // [k=512][n=256]
    int idx = blockIdx.x * 256 + threadIdx.x;          // 131072
    int k = idx >> 8, n = idx & 255;
    g_Wh[n*FF + k] = __float2half_rn(We[k*HH + n]);
}

// ---- kernel 2: fp16 mma.sync scores GEMM + fused softmax-partial + ctx ----
// Per CTA: 64 s-rows x 256 h-cols x K=512.  256 threads, 8 warps (2m x 4n),
// warp tile 32x64, occupancy 2. After the GEMM: per-tile max/exp/sum and
// partial context (re-reads own E tile fp32, overlapped across CTAs).
#define STAGE   40960                // A 8KB + B 32KB
#define A_OFF   0
#define B_OFF   8192
#define SM_QW   (2*STAGE)
#define SM_V    (SM_QW + 1024)
#define SM_RED  (SM_V + 1024)
#define SM_SW   (SM_RED + 1024)
#define SM_MR   (SM_SW + 256)
#define SM_CTX  (SM_MR + 128)
#define SMEM_SC (SM_CTX + 2048)

__global__ void __launch_bounds__(256, 2)
scores_mma(const float* __restrict__ E, const float* __restrict__ v)
{
    extern __shared__ char sm[];
    const uint32_t smb = smem_u32(sm);
    const int tid  = threadIdx.x;
    const int lane = tid & 31, warp = tid >> 5;
    const int wm = warp >> 2, wn = warp & 3;       // 2 x 4 warp grid
    const int tile = blockIdx.x;
    const int s0 = tile * 64;
    const int b  = blockIdx.y;

    float* sq = (float*)(sm + SM_QW);
    float* sv = (float*)(sm + SM_V);
    sq[tid] = g_qWh[b*HH + tid];
    sv[tid] = v[tid];

    // A producer mapping: row0 = tid>>2 (0..63), seg = tid&3 (16 k each)
    const int seg  = tid & 3;
    const int row0 = tid >> 2;
    const float* Ap = E + ((long)(b*SS + s0 + row0))*FF + seg*16;
    const uint32_t dA0 = sw128(row0, seg*2);
    const uint32_t dA1 = sw128(row0, seg*2 + 1);

    float acc[2][8][4];
#pragma unroll
    for (int mt = 0; mt < 2; mt++)
#pragma unroll
        for (int nt = 0; nt < 8; nt++)
#pragma unroll
            for (int e = 0; e < 4; e++) acc[mt][nt][e] = 0.0f;

#define B_FETCH(stp, k0)                                                         \
    do {                                                                         \
        _Pragma("unroll")                                                        \
        for (int j = 0; j < 8; j++) {                                            \
            int idx = tid + 256*j;                                               \
            int br = idx >> 3, bc = idx & 7;                                     \
            cp_async16((stp) + B_OFF + sw128(br, bc),                            \
                       g_Wh + (long)br*FF + (k0) + bc*8);                        \
        }                                                                        \
        CP_COMMIT();                                                             \
    } while (0)

#define A_STORE(stp, f0, f1, f2, f3)                                             \
    do {                                                                         \
        __half2 h0 = __floats2half2_rn((f0).x, (f0).y);                          \
        __half2 h1 = __floats2half2_rn((f0).z, (f0).w);                          \
        __half2 h2 = __floats2half2_rn((f1).x, (f1).y);                          \
        __half2 h3 = __floats2half2_rn((f1).z, (f1).w);                          \
        __half2 h4 = __floats2half2_rn((f2).x, (f2).y);                          \
        __half2 h5 = __floats2half2_rn((f2).z, (f2).w);                          \
        __half2 h6 = __floats2half2_rn((f3).x, (f3).y);                          \
        __half2 h7 = __floats2half2_rn((f3).z, (f3).w);                          \
        *(uint4*)((stp) + A_OFF + dA0) = make_uint4(                             \
            *(uint32_t*)&h0, *(uint32_t*)&h1, *(uint32_t*)&h2, *(uint32_t*)&h3); \
        *(uint4*)((stp) + A_OFF + dA1) = make_uint4(                             \
            *(uint32_t*)&h4, *(uint32_t*)&h5, *(uint32_t*)&h6, *(uint32_t*)&h7); \
    } while (0)

    // ---- prologue: chunk 0 into stage 0 ----
    {
        B_FETCH(sm, 0);
        float4 f0 = *(const float4*)(Ap);
        float4 f1 = *(const float4*)(Ap + 4);
        float4 f2 = *(const float4*)(Ap + 8);
        float4 f3 = *(const float4*)(Ap + 12);
        A_STORE(sm, f0, f1, f2, f3);
        CP_WAIT0();
        __syncthreads();
    }

    for (int c = 0; c < 8; c++) {
        const int cur = c & 1;
        char* stn = sm + (cur ^ 1)*STAGE;
        const uint32_t stcb = smb + cur*STAGE;

        float4 f0, f1, f2, f3;
        if (c < 7) {
            const int k1 = (c + 1)*64;
            B_FETCH(stn, k1);
            f0 = *(const float4*)(Ap + k1);
            f1 = *(const float4*)(Ap + k1 + 4);
            f2 = *(const float4*)(Ap + k1 + 8);
            f3 = *(const float4*)(Ap + k1 + 12);
        }

#pragma unroll
        for (int ks = 0; ks < 4; ks++) {
            uint32_t af[2][4];
#pragma unroll
            for (int mt = 0; mt < 2; mt++) {
                int r = wm*32 + mt*16 + (lane & 15);
                ldsm_x4(af[mt], stcb + A_OFF + sw128(r, ks*2 + (lane >> 4)));
            }
#pragma unroll
            for (int nb = 0; nb < 4; nb++) {
                int nr = wn*64 + nb*16 + ((lane >> 4) << 3) + (lane & 7);
                int cc = ks*2 + ((lane >> 3) & 1);
                uint32_t r4[4];
                ldsm_x4(r4, stcb + B_OFF + sw128(nr, cc));
                uint32_t b0[2] = { r4[0], r4[1] };
                uint32_t b1[2] = { r4[2], r4[3] };
#pragma unroll
                for (int mt = 0; mt < 2; mt++) {
                    mma_fp16(acc[mt][nb*2],     af[mt], b0);
                    mma_fp16(acc[mt][nb*2 + 1], af[mt], b1);
                }
            }
        }

        if (c < 7) {
            A_STORE(stn, f0, f1, f2, f3);
            CP_WAIT0();
        }
        __syncthreads();
    }

    // ---- epilogue 1: +qWh, tanh, dot v -> per-row scores in red[] ----
    float* red = (float*)(sm + SM_RED);   // [64 rows][4 n-warp groups]
#pragma unroll
    for (int mt = 0; mt < 2; mt++) {
        float pA = 0.0f, pB = 0.0f;
#pragma unroll
        for (int nt = 0; nt < 8; nt++) {
            int h0 = wn*64 + nt*8 + (lane & 3)*2;
            float q0 = sq[h0], q1 = sq[h0 + 1];
            float v0 = sv[h0], v1 = sv[h0 + 1];
            pA += v0*tanhf(acc[mt][nt][0] + q0) + v1*tanhf(acc[mt][nt][1] + q1);
            pB += v0*tanhf(acc[mt][nt][2] + q0) + v1*tanhf(acc[mt][nt][3] + q1);
        }
        pA += __shfl_xor_sync(0xffffffffu, pA, 1);
        pA += __shfl_xor_sync(0xffffffffu, pA, 2);
        pB += __shfl_xor_sync(0xffffffffu, pB, 1);
        pB += __shfl_xor_sync(0xffffffffu, pB, 2);
        if ((lane & 3) == 0) {
            int r = wm*32 + mt*16 + (lane >> 2);
            red[r*4 + wn]       = pA;
            red[(r + 8)*4 + wn] = pB;
        }
    }
    __syncthreads();

    // ---- epilogue 2: local softmax stats (m, w_r, S) ----
    float* mr  = (float*)(sm + SM_MR);
    float* swm = (float*)(sm + SM_SW);
    float s_loc = 0.0f;
    if (tid < 64)
        s_loc = red[tid*4] + red[tid*4+1] + red[tid*4+2] + red[tid*4+3];
    float mv = (tid < 64) ? s_loc : -3.0e38f;
#pragma unroll
    for (int o = 16; o; o >>= 1) mv = fmaxf(mv, __shfl_xor_sync(0xffffffffu, mv, o));
    if (tid < 64 && lane == 0) mr[warp] = mv;
    __syncthreads();
    const float mtile = fmaxf(mr[0], mr[1]);
    float wv = 0.0f;
    if (tid < 64) { wv = expf(s_loc - mtile); swm[tid] = wv; }
    float sv2 = (tid < 64) ? wv : 0.0f;
#pragma unroll
    for (int o = 16; o; o >>= 1) sv2 += __shfl_xor_sync(0xffffffffu, sv2, o);
    if (tid < 64 && lane == 0) mr[2 + warp] = sv2;
    __syncthreads();
    if (tid == 0)
        g_ms[b*NTILE + tile] = make_float2(mtile, mr[2] + mr[3]);

    // ---- epilogue 3: partial context = sum_r w_r * E[s0+r][f] (fp32) ----
    {
        float4* sctx = (float4*)(sm + SM_CTX);
        const int rg = tid >> 7;             // 0..1 (rows 0-31 / 32-63)
        const int fq = (tid & 127) * 4;
        const float* Eb = E + ((long)(b*SS + s0 + rg*32))*FF + fq;
        float4 a4 = make_float4(0.f, 0.f, 0.f, 0.f);
#pragma unroll 8
        for (int r = 0; r < 32; r++) {
            float w2 = swm[rg*32 + r];
            float4 e = *(const float4*)(Eb + (long)r*FF);
            a4.x += w2*e.x; a4.y += w2*e.y; a4.z += w2*e.z; a4.w += w2*e.w;
        }
        if (rg == 1) sctx[tid & 127] = a4;
        __syncthreads();
        if (rg == 0) {
            float4 o4 = sctx[tid];
            o4.x += a4.x; o4.y += a4.y; o4.z += a4.z; o4.w += a4.w;
            *(float4*)(&g_part[((long)tile*BB + b)*FF + fq]) = o4;
        }
    }
}

// ---- kernel 3: combine partials (max-corrected) + GRU + output proj ----
__global__ void gru_kernel(const float* __restrict__ w_ih, const float* __restrict__ b_ih,
                           const float* __restrict__ b_hh, const float* __restrict__ out_W,
                           const float* __restrict__ out_b, float* __restrict__ out,
                           int out_size)
{
    __shared__ float x[3*HH];
    __shared__ float g[3*HH];
    __shared__ float h[HH];
    __shared__ float fc[NTILE];
    __shared__ float r4[8];
    const int b = blockIdx.x, tid = threadIdx.x; // 256 threads
    const int lane = tid & 31;

    // combine softmax stats across 64 tiles
    float2 ms = make_float2(-3.0e38f, 0.0f);
    if (tid < NTILE) ms = g_ms[b*NTILE + tid];
    float mv = ms.x;
#pragma unroll
    for (int o = 16; o; o >>= 1) mv = fmaxf(mv, __shfl_xor_sync(0xffffffffu, mv, o));
    if (tid < NTILE && lane == 0) r4[tid >> 5] = mv;
    __syncthreads();
    const float M = fmaxf(r4[0], r4[1]);
    float Sv = 0.0f;
    if (tid < NTILE) {
        float f_c = expf(ms.x - M);
        fc[tid] = f_c;
        Sv = ms.y * f_c;
    }
#pragma unroll
    for (int o = 16; o; o >>= 1) Sv += __shfl_xor_sync(0xffffffffu, Sv, o);
    if (tid < NTILE && lane == 0) r4[2 + (tid >> 5)] = Sv;
    __syncthreads();
    const float inv_den = 1.0f / (r4[2] + r4[3]);

    // context = (sum_c part[c][b][f] * fc[c]) * inv_den
#pragma unroll
    for (int rr = 0; rr < 2; rr++) {
        const int f = tid + rr*256;
        float acc = 0.0f;
#pragma unroll 8
        for (int c = 0; c < NTILE; c++)
            acc += g_part[((long)c*BB + b)*FF + f] * fc[c];
        x[HH + f] = acc * inv_den;
    }
    x[tid] = g_embT[b*HH + tid];
    __syncthreads();

    // gi = x @ w_ih + b_ih   (768x768)
#pragma unroll
    for (int r = 0; r < 3; r++) {
        const int jj = tid + r*256;
        float acc = b_ih[jj];
#pragma unroll 8
        for (int k = 0; k < 3*HH; k++) acc += x[k] * w_ih[k*(3*HH) + jj];
        g[jj] = acc;
    }
    __syncthreads();

    {
        const int j = tid;
        const float rg = sigmoidf_(g[j]        + b_hh[j]);
        const float zg = sigmoidf_(g[HH + j]   + b_hh[HH + j]);
        const float ng = tanhf   (g[2*HH + j]  + rg * b_hh[2*HH + j]);
        const float hv = (1.0f - zg) * ng;
        h[j] = hv;
        const int ho = BB*OUTD + b*HH + j;
        if (ho < out_size) out[ho] = hv;
    }
    __syncthreads();

    if (tid < OUTD) {
        float acc = out_b[tid];
#pragma unroll 8
        for (int k = 0; k < HH; k++) acc += h[k] * out_W[k*OUTD + tid];
        out[b*OUTD + tid] = acc;
    }
}

// ---------------- launch ----------------
extern "C" void kernel_launch(void* const* d_in, const int* in_sizes, int n_in,
                              void* d_out, int out_size)
{
    const int*   fc     = (const int*)  d_in[0];   // fut_ctxt (B,1)
    const int*   ft     = (const int*)  d_in[1];   // fut_temp (B,1)
    const float* E      = (const float*)d_in[2];   // encoder_outputs (B,S,2H)
    const float* emb_c  = (const float*)d_in[3];   // emb_ctxt (1000,H)
    const float* emb_t  = (const float*)d_in[4];   // emb_temp (1000,H)
    const float* attn_W = (const float*)d_in[5];   // (3H,H)
    const float* attn_b = (const float*)d_in[6];   // (H,)
    const float* v      = (const float*)d_in[7];   // (H,)
    const float* w_ih   = (const float*)d_in[8];   // (3H,3H)
    // d_in[9] = w_hh: unused since h0 == 0 (gh = b_hh exactly)
    const float* b_ih   = (const float*)d_in[10];  // (3H,)
    const float* b_hh   = (const float*)d_in[11];  // (3H,)
    const float* out_W  = (const float*)d_in[12];  // (H,OUT)
    const float* out_b  = (const float*)d_in[13];  // (OUT,)
    float* out = (float*)d_out;

    cudaFuncSetAttribute(scores_mma, cudaFuncAttributeMaxDynamicSharedMemorySize,
                         SMEM_SC);

    setup_kernel<<<BB, HH>>>(fc, ft, emb_c, emb_t, attn_W, attn_b);
    prep_W<<<512, 256>>>(attn_W);
    scores_mma<<<dim3(NTILE, BB), 256, SMEM_SC>>>(E, v);
    gru_kernel<<<BB, 256>>>(w_ih, b_ih, b_hh, out_W, out_b, out, out_size);
}

// round 14
// speedup vs baseline: 2.4319x; 1.4584x over previous
#include <cuda_runtime.h>
#include <cuda_fp16.h>
#include <cstdint>

#define BB   64
#define SS   4096
#define HH   256
#define FF   512      // 2*H
#define OUTD 24
#define NTILE 64      // s-tiles per batch (64 rows each)

// ---------------- scratch (static device globals; no allocs) ----------------
__device__ __align__(16) float g_qWh[BB*HH];      // hidden_q @ W_h + attn_b
__device__ __align__(16) float g_embT[BB*HH];     // gathered emb_temp
__device__ __align__(16) float g_part[NTILE*BB*FF]; // ctx partials per tile
__device__ __align__(16) float2 g_ms[BB*NTILE];   // (local max, local expsum)
__device__ __align__(16) __half g_Wh[HH*FF];      // W_e^T fp16 [n=256][k=512]

// ---------------- helpers ----------------
__device__ __forceinline__ uint32_t smem_u32(const void* p) {
    uint32_t a;
    asm("{ .reg .u64 t; cvta.to.shared.u64 t, %1; cvt.u32.u64 %0, t; }"
        : "=r"(a) : "l"(p));
    return a;
}
__device__ __forceinline__ void cp_async16(void* sm, const void* g) {
    unsigned s = (unsigned)__cvta_generic_to_shared(sm);
    asm volatile("cp.async.cg.shared.global [%0], [%1], 16;" :: "r"(s), "l"(g));
}
#define CP_COMMIT() asm volatile("cp.async.commit_group;")
#define CP_WAIT0()  asm volatile("cp.async.wait_group 0;")

__device__ __forceinline__ void ldsm_x4(uint32_t* r, uint32_t addr) {
    asm volatile("ldmatrix.sync.aligned.m8n8.x4.shared.b16 {%0,%1,%2,%3}, [%4];"
        : "=r"(r[0]), "=r"(r[1]), "=r"(r[2]), "=r"(r[3]) : "r"(addr));
}
__device__ __forceinline__ void mma_fp16(float* c, const uint32_t* a, const uint32_t* b) {
    asm volatile("mma.sync.aligned.m16n8k16.row.col.f32.f16.f16.f32 "
        "{%0,%1,%2,%3}, {%4,%5,%6,%7}, {%8,%9}, {%0,%1,%2,%3};"
        : "+f"(c[0]), "+f"(c[1]), "+f"(c[2]), "+f"(c[3])
        : "r"(a[0]), "r"(a[1]), "r"(a[2]), "r"(a[3]), "r"(b[0]), "r"(b[1]));
}
// 128B-row swizzle: 16B chunk c (0..7) of row r
__device__ __forceinline__ uint32_t sw128(int r, int c) {
    return (uint32_t)(r*128 + ((c ^ (r & 7)) << 4));
}
__device__ __forceinline__ float sigmoidf_(float x) { return 1.0f / (1.0f + expf(-x)); }

// ---------------- kernel 1: gathers + qWh = emb_ctxt[idx] @ W_h + attn_b ----
__global__ void setup_kernel(const int* __restrict__ fc, const int* __restrict__ ft,
                             const float* __restrict__ emb_c, const float* __restrict__ emb_t,
                             const float* __restrict__ attn_W, const float* __restrict__ attn_b)
{
    __shared__ float q[HH];
    int b = blockIdx.x, tid = threadIdx.x;
    int ci = fc[b], ti = ft[b];
    q[tid] = emb_c[ci*HH + tid];
    g_embT[b*HH + tid] = emb_t[ti*HH + tid];
    __syncthreads();
    float acc = attn_b[tid];
#pragma unroll 8
    for (int k = 0; k < HH; k++) acc += q[k] * attn_W[k*HH + tid];
    g_qWh[b*HH + tid] = acc;
}

// ---------------- kernel 1b: W_e transpose + fp16 convert ----------------
__global__ void prep_W(const float* __restrict__ attn_W)
{
    const float* We = attn_W + HH*HH;                  // [k=512][n=256]
    int idx = blockIdx.x * 256 + threadIdx.x;          // 131072
    int k = idx >> 8, n = idx & 255;
    g_Wh[n*FF + k] = __float2half_rn(We[k*HH + n]);
}

// ---- kernel 2: fp16 mma.sync scores GEMM + fused softmax-partial + ctx ----
// (unchanged from R13 — at the legacy-HMMA issue ceiling)
#define STAGE   40960                // A 8KB + B 32KB
#define A_OFF   0
#define B_OFF   8192
#define SM_QW   (2*STAGE)
#define SM_V    (SM_QW + 1024)
#define SM_RED  (SM_V + 1024)
#define SM_SW   (SM_RED + 1024)
#define SM_MR   (SM_SW + 256)
#define SM_CTX  (SM_MR + 128)
#define SMEM_SC (SM_CTX + 2048)

__global__ void __launch_bounds__(256, 2)
scores_mma(const float* __restrict__ E, const float* __restrict__ v)
{
    extern __shared__ char sm[];
    const uint32_t smb = smem_u32(sm);
    const int tid  = threadIdx.x;
    const int lane = tid & 31, warp = tid >> 5;
    const int wm = warp >> 2, wn = warp & 3;       // 2 x 4 warp grid
    const int tile = blockIdx.x;
    const int s0 = tile * 64;
    const int b  = blockIdx.y;

    float* sq = (float*)(sm + SM_QW);
    float* sv = (float*)(sm + SM_V);
    sq[tid] = g_qWh[b*HH + tid];
    sv[tid] = v[tid];

    const int seg  = tid & 3;
    const int row0 = tid >> 2;
    const float* Ap = E + ((long)(b*SS + s0 + row0))*FF + seg*16;
    const uint32_t dA0 = sw128(row0, seg*2);
    const uint32_t dA1 = sw128(row0, seg*2 + 1);

    float acc[2][8][4];
#pragma unroll
    for (int mt = 0; mt < 2; mt++)
#pragma unroll
        for (int nt = 0; nt < 8; nt++)
#pragma unroll
            for (int e = 0; e < 4; e++) acc[mt][nt][e] = 0.0f;

#define B_FETCH(stp, k0)                                                         \
    do {                                                                         \
        _Pragma("unroll")                                                        \
        for (int j = 0; j < 8; j++) {                                            \
            int idx = tid + 256*j;                                               \
            int br = idx >> 3, bc = idx & 7;                                     \
            cp_async16((stp) + B_OFF + sw128(br, bc),                            \
                       g_Wh + (long)br*FF + (k0) + bc*8);                        \
        }                                                                        \
        CP_COMMIT();                                                             \
    } while (0)

#define A_STORE(stp, f0, f1, f2, f3)                                             \
    do {                                                                         \
        __half2 h0 = __floats2half2_rn((f0).x, (f0).y);                          \
        __half2 h1 = __floats2half2_rn((f0).z, (f0).w);                          \
        __half2 h2 = __floats2half2_rn((f1).x, (f1).y);                          \
        __half2 h3 = __floats2half2_rn((f1).z, (f1).w);                          \
        __half2 h4 = __floats2half2_rn((f2).x, (f2).y);                          \
        __half2 h5 = __floats2half2_rn((f2).z, (f2).w);                          \
        __half2 h6 = __floats2half2_rn((f3).x, (f3).y);                          \
        __half2 h7 = __floats2half2_rn((f3).z, (f3).w);                          \
        *(uint4*)((stp) + A_OFF + dA0) = make_uint4(                             \
            *(uint32_t*)&h0, *(uint32_t*)&h1, *(uint32_t*)&h2, *(uint32_t*)&h3); \
        *(uint4*)((stp) + A_OFF + dA1) = make_uint4(                             \
            *(uint32_t*)&h4, *(uint32_t*)&h5, *(uint32_t*)&h6, *(uint32_t*)&h7); \
    } while (0)

    {
        B_FETCH(sm, 0);
        float4 f0 = *(const float4*)(Ap);
        float4 f1 = *(const float4*)(Ap + 4);
        float4 f2 = *(const float4*)(Ap + 8);
        float4 f3 = *(const float4*)(Ap + 12);
        A_STORE(sm, f0, f1, f2, f3);
        CP_WAIT0();
        __syncthreads();
    }

    for (int c = 0; c < 8; c++) {
        const int cur = c & 1;
        char* stn = sm + (cur ^ 1)*STAGE;
        const uint32_t stcb = smb + cur*STAGE;

        float4 f0, f1, f2, f3;
        if (c < 7) {
            const int k1 = (c + 1)*64;
            B_FETCH(stn, k1);
            f0 = *(const float4*)(Ap + k1);
            f1 = *(const float4*)(Ap + k1 + 4);
            f2 = *(const float4*)(Ap + k1 + 8);
            f3 = *(const float4*)(Ap + k1 + 12);
        }

#pragma unroll
        for (int ks = 0; ks < 4; ks++) {
            uint32_t af[2][4];
#pragma unroll
            for (int mt = 0; mt < 2; mt++) {
                int r = wm*32 + mt*16 + (lane & 15);
                ldsm_x4(af[mt], stcb + A_OFF + sw128(r, ks*2 + (lane >> 4)));
            }
#pragma unroll
            for (int nb = 0; nb < 4; nb++) {
                int nr = wn*64 + nb*16 + ((lane >> 4) << 3) + (lane & 7);
                int cc = ks*2 + ((lane >> 3) & 1);
                uint32_t r4[4];
                ldsm_x4(r4, stcb + B_OFF + sw128(nr, cc));
                uint32_t b0[2] = { r4[0], r4[1] };
                uint32_t b1[2] = { r4[2], r4[3] };
#pragma unroll
                for (int mt = 0; mt < 2; mt++) {
                    mma_fp16(acc[mt][nb*2],     af[mt], b0);
                    mma_fp16(acc[mt][nb*2 + 1], af[mt], b1);
                }
            }
        }

        if (c < 7) {
            A_STORE(stn, f0, f1, f2, f3);
            CP_WAIT0();
        }
        __syncthreads();
    }

    // ---- epilogue 1: +qWh, tanh, dot v -> per-row scores in red[] ----
    float* red = (float*)(sm + SM_RED);   // [64 rows][4 n-warp groups]
#pragma unroll
    for (int mt = 0; mt < 2; mt++) {
        float pA = 0.0f, pB = 0.0f;
#pragma unroll
        for (int nt = 0; nt < 8; nt++) {
            int h0 = wn*64 + nt*8 + (lane & 3)*2;
            float q0 = sq[h0], q1 = sq[h0 + 1];
            float v0 = sv[h0], v1 = sv[h0 + 1];
            pA += v0*tanhf(acc[mt][nt][0] + q0) + v1*tanhf(acc[mt][nt][1] + q1);
            pB += v0*tanhf(acc[mt][nt][2] + q0) + v1*tanhf(acc[mt][nt][3] + q1);
        }
        pA += __shfl_xor_sync(0xffffffffu, pA, 1);
        pA += __shfl_xor_sync(0xffffffffu, pA, 2);
        pB += __shfl_xor_sync(0xffffffffu, pB, 1);
        pB += __shfl_xor_sync(0xffffffffu, pB, 2);
        if ((lane & 3) == 0) {
            int r = wm*32 + mt*16 + (lane >> 2);
            red[r*4 + wn]       = pA;
            red[(r + 8)*4 + wn] = pB;
        }
    }
    __syncthreads();

    // ---- epilogue 2: local softmax stats (m, w_r, S) ----
    float* mr  = (float*)(sm + SM_MR);
    float* swm = (float*)(sm + SM_SW);
    float s_loc = 0.0f;
    if (tid < 64)
        s_loc = red[tid*4] + red[tid*4+1] + red[tid*4+2] + red[tid*4+3];
    float mv = (tid < 64) ? s_loc : -3.0e38f;
#pragma unroll
    for (int o = 16; o; o >>= 1) mv = fmaxf(mv, __shfl_xor_sync(0xffffffffu, mv, o));
    if (tid < 64 && lane == 0) mr[warp] = mv;
    __syncthreads();
    const float mtile = fmaxf(mr[0], mr[1]);
    float wv = 0.0f;
    if (tid < 64) { wv = expf(s_loc - mtile); swm[tid] = wv; }
    float sv2 = (tid < 64) ? wv : 0.0f;
#pragma unroll
    for (int o = 16; o; o >>= 1) sv2 += __shfl_xor_sync(0xffffffffu, sv2, o);
    if (tid < 64 && lane == 0) mr[2 + warp] = sv2;
    __syncthreads();
    if (tid == 0)
        g_ms[b*NTILE + tile] = make_float2(mtile, mr[2] + mr[3]);

    // ---- epilogue 3: partial context = sum_r w_r * E[s0+r][f] (fp32) ----
    {
        float4* sctx = (float4*)(sm + SM_CTX);
        const int rg = tid >> 7;             // 0..1 (rows 0-31 / 32-63)
        const int fq = (tid & 127) * 4;
        const float* Eb = E + ((long)(b*SS + s0 + rg*32))*FF + fq;
        float4 a4 = make_float4(0.f, 0.f, 0.f, 0.f);
#pragma unroll 8
        for (int r = 0; r < 32; r++) {
            float w2 = swm[rg*32 + r];
            float4 e = *(const float4*)(Eb + (long)r*FF);
            a4.x += w2*e.x; a4.y += w2*e.y; a4.z += w2*e.z; a4.w += w2*e.w;
        }
        if (rg == 1) sctx[tid & 127] = a4;
        __syncthreads();
        if (rg == 0) {
            float4 o4 = sctx[tid];
            o4.x += a4.x; o4.y += a4.y; o4.z += a4.z; o4.w += a4.w;
            *(float4*)(&g_part[((long)tile*BB + b)*FF + fq]) = o4;
        }
    }
}

// ---- kernel 3: combine partials (max-corrected) + GRU + output proj ----
// 768 threads: parallel ctx reduce, 1 thread per gi output (deep-unrolled
// coalesced k-loop), warp-per-output projection.
__global__ void __launch_bounds__(768)
gru_kernel(const float* __restrict__ w_ih, const float* __restrict__ b_ih,
           const float* __restrict__ b_hh, const float* __restrict__ out_W,
           const float* __restrict__ out_b, float* __restrict__ out,
           int out_size)
{
    __shared__ __align__(16) float x[3*HH];
    __shared__ float g[3*HH];
    __shared__ float h[HH];
    __shared__ float fc[NTILE];
    __shared__ float r4[8];
    __shared__ float sW[HH*OUTD];   // out_W staged (24.5 KB)
    const int b = blockIdx.x, tid = threadIdx.x;
    const int lane = tid & 31, warp = tid >> 5;

    // stage out_W while stats combine happens
    for (int i = tid; i < HH*OUTD; i += 768) sW[i] = out_W[i];

    // combine softmax stats across 64 tiles
    float2 ms = make_float2(-3.0e38f, 0.0f);
    if (tid < NTILE) ms = g_ms[b*NTILE + tid];
    float mv = ms.x;
#pragma unroll
    for (int o = 16; o; o >>= 1) mv = fmaxf(mv, __shfl_xor_sync(0xffffffffu, mv, o));
    if (tid < NTILE && lane == 0) r4[warp] = mv;
    __syncthreads();
    const float M = fmaxf(r4[0], r4[1]);
    float Sv = 0.0f;
    if (tid < NTILE) {
        float f_c = expf(ms.x - M);
        fc[tid] = f_c;
        Sv = ms.y * f_c;
    }
#pragma unroll
    for (int o = 16; o; o >>= 1) Sv += __shfl_xor_sync(0xffffffffu, Sv, o);
    if (tid < NTILE && lane == 0) r4[2 + warp] = Sv;
    __syncthreads();
    const float inv_den = 1.0f / (r4[2] + r4[3]);

    // x[0:256] = embT (threads 512-767), x[256:768] = ctx (threads 0-511)
    if (tid < 512) {
        const int f = tid;
        float acc = 0.0f;
#pragma unroll 8
        for (int c = 0; c < NTILE; c++)
            acc += g_part[((long)c*BB + b)*FF + f] * fc[c];
        x[HH + f] = acc * inv_den;
    } else {
        x[tid - 512] = g_embT[b*HH + tid - 512];
    }
    __syncthreads();

    // gi = x @ w_ih + b_ih : one thread per output jj (coalesced k-loop)
    {
        const int jj = tid;
        float acc = b_ih[jj];
        const float* wp = w_ih + jj;
#pragma unroll 16
        for (int k = 0; k < 3*HH; k++) acc += x[k] * wp[k*(3*HH)];
        g[jj] = acc;
    }
    __syncthreads();

    // gates (h0 = 0 => gh = b_hh exactly)
    if (tid < HH) {
        const int j = tid;
        const float rg = sigmoidf_(g[j]        + b_hh[j]);
        const float zg = sigmoidf_(g[HH + j]   + b_hh[HH + j]);
        const float ng = tanhf   (g[2*HH + j]  + rg * b_hh[2*HH + j]);
        const float hv = (1.0f - zg) * ng;
        h[j] = hv;
        const int ho = BB*OUTD + b*HH + j;
        if (ho < out_size) out[ho] = hv;
    }
    __syncthreads();

    // output = h @ out_W + out_b : warp per output, lanes over k
    if (warp < OUTD) {
        float p = 0.0f;
#pragma unroll
        for (int i = 0; i < 8; i++) {
            int k = lane + i*32;
            p += h[k] * sW[k*OUTD + warp];
        }
#pragma unroll
        for (int o = 16; o; o >>= 1) p += __shfl_xor_sync(0xffffffffu, p, o);
        if (lane == 0) out[b*OUTD + warp] = p + out_b[warp];
    }
}

// ---------------- launch ----------------
extern "C" void kernel_launch(void* const* d_in, const int* in_sizes, int n_in,
                              void* d_out, int out_size)
{
    const int*   fc     = (const int*)  d_in[0];   // fut_ctxt (B,1)
    const int*   ft     = (const int*)  d_in[1];   // fut_temp (B,1)
    const float* E      = (const float*)d_in[2];   // encoder_outputs (B,S,2H)
    const float* emb_c  = (const float*)d_in[3];   // emb_ctxt (1000,H)
    const float* emb_t  = (const float*)d_in[4];   // emb_temp (1000,H)
    const float* attn_W = (const float*)d_in[5];   // (3H,H)
    const float* attn_b = (const float*)d_in[6];   // (H,)
    const float* v      = (const float*)d_in[7];   // (H,)
    const float* w_ih   = (const float*)d_in[8];   // (3H,3H)
    // d_in[9] = w_hh: unused since h0 == 0 (gh = b_hh exactly)
    const float* b_ih   = (const float*)d_in[10];  // (3H,)
    const float* b_hh   = (const float*)d_in[11];  // (3H,)
    const float* out_W  = (const float*)d_in[12];  // (H,OUT)
    const float* out_b  = (const float*)d_in[13];  // (OUT,)
    float* out = (float*)d_out;

    cudaFuncSetAttribute(scores_mma, cudaFuncAttributeMaxDynamicSharedMemorySize,
                         SMEM_SC);

    setup_kernel<<<BB, HH>>>(fc, ft, emb_c, emb_t, attn_W, attn_b);
    prep_W<<<512, 256>>>(attn_W);
    scores_mma<<<dim3(NTILE, BB), 256, SMEM_SC>>>(E, v);
    gru_kernel<<<BB, 768>>>(w_ih, b_ih, b_hh, out_W, out_b, out, out_size);
}

// round 15
// speedup vs baseline: 2.4626x; 1.0126x over previous
#include <cuda_runtime.h>
#include <cuda_fp16.h>
#include <cstdint>

#define BB   64
#define SS   4096
#define HH   256
#define FF   512      // 2*H
#define OUTD 24
#define NTILE 64      // s-tiles per batch (64 rows each)

// ---------------- scratch (static device globals; no allocs) ----------------
__device__ __align__(16) float g_qWh[BB*HH];      // hidden_q @ W_h + attn_b
__device__ __align__(16) float g_embT[BB*HH];     // gathered emb_temp
__device__ __align__(16) float g_part[NTILE*BB*FF]; // ctx partials per tile
__device__ __align__(16) float2 g_ms[BB*NTILE];   // (local max, local expsum)
__device__ __align__(16) __half g_Wh[HH*FF];      // W_e^T fp16 [n=256][k=512]

// ---------------- helpers ----------------
__device__ __forceinline__ uint32_t smem_u32(const void* p) {
    uint32_t a;
    asm("{ .reg .u64 t; cvta.to.shared.u64 t, %1; cvt.u32.u64 %0, t; }"
        : "=r"(a) : "l"(p));
    return a;
}
__device__ __forceinline__ void cp_async16(void* sm, const void* g) {
    unsigned s = (unsigned)__cvta_generic_to_shared(sm);
    asm volatile("cp.async.cg.shared.global [%0], [%1], 16;" :: "r"(s), "l"(g));
}
#define CP_COMMIT() asm volatile("cp.async.commit_group;")
#define CP_WAIT0()  asm volatile("cp.async.wait_group 0;")

__device__ __forceinline__ void ldsm_x4(uint32_t* r, uint32_t addr) {
    asm volatile("ldmatrix.sync.aligned.m8n8.x4.shared.b16 {%0,%1,%2,%3}, [%4];"
        : "=r"(r[0]), "=r"(r[1]), "=r"(r[2]), "=r"(r[3]) : "r"(addr));
}
__device__ __forceinline__ void mma_fp16(float* c, const uint32_t* a, const uint32_t* b) {
    asm volatile("mma.sync.aligned.m16n8k16.row.col.f32.f16.f16.f32 "
        "{%0,%1,%2,%3}, {%4,%5,%6,%7}, {%8,%9}, {%0,%1,%2,%3};"
        : "+f"(c[0]), "+f"(c[1]), "+f"(c[2]), "+f"(c[3])
        : "r"(a[0]), "r"(a[1]), "r"(a[2]), "r"(a[3]), "r"(b[0]), "r"(b[1]));
}
// 128B-row swizzle: 16B chunk c (0..7) of row r
__device__ __forceinline__ uint32_t sw128(int r, int c) {
    return (uint32_t)(r*128 + ((c ^ (r & 7)) << 4));
}
__device__ __forceinline__ float sigmoidf_(float x) { return 1.0f / (1.0f + expf(-x)); }

// ---- kernel 1: fused prep: W_e^T fp16 split (blocks 0-511) +
//      gathers & qWh (blocks 512-575) ----
__global__ void setup_prep(const int* __restrict__ fc, const int* __restrict__ ft,
                           const float* __restrict__ emb_c, const float* __restrict__ emb_t,
                           const float* __restrict__ attn_W, const float* __restrict__ attn_b)
{
    const int tid = threadIdx.x;
    if (blockIdx.x < 512) {
        const float* We = attn_W + HH*HH;              // [k=512][n=256]
        int idx = blockIdx.x * 256 + tid;
        int k = idx >> 8, n = idx & 255;
        g_Wh[n*FF + k] = __float2half_rn(We[k*HH + n]);
    } else {
        __shared__ float q[HH];
        int b = blockIdx.x - 512;
        int ci = fc[b], ti = ft[b];
        q[tid] = emb_c[ci*HH + tid];
        g_embT[b*HH + tid] = emb_t[ti*HH + tid];
        __syncthreads();
        float acc = attn_b[tid];
#pragma unroll 8
        for (int k = 0; k < HH; k++) acc += q[k] * attn_W[k*HH + tid];
        g_qWh[b*HH + tid] = acc;
    }
}

// ---- kernel 2: fp16 mma.sync scores GEMM + fused softmax-partial + ctx ----
// (unchanged from R13/R14 — at the legacy-HMMA issue ceiling)
#define STAGE   40960                // A 8KB + B 32KB
#define A_OFF   0
#define B_OFF   8192
#define SM_QW   (2*STAGE)
#define SM_V    (SM_QW + 1024)
#define SM_RED  (SM_V + 1024)
#define SM_SW   (SM_RED + 1024)
#define SM_MR   (SM_SW + 256)
#define SM_CTX  (SM_MR + 128)
#define SMEM_SC (SM_CTX + 2048)

__global__ void __launch_bounds__(256, 2)
scores_mma(const float* __restrict__ E, const float* __restrict__ v)
{
    extern __shared__ char sm[];
    const uint32_t smb = smem_u32(sm);
    const int tid  = threadIdx.x;
    const int lane = tid & 31, warp = tid >> 5;
    const int wm = warp >> 2, wn = warp & 3;       // 2 x 4 warp grid
    const int tile = blockIdx.x;
    const int s0 = tile * 64;
    const int b  = blockIdx.y;

    float* sq = (float*)(sm + SM_QW);
    float* sv = (float*)(sm + SM_V);
    sq[tid] = g_qWh[b*HH + tid];
    sv[tid] = v[tid];

    const int seg  = tid & 3;
    const int row0 = tid >> 2;
    const float* Ap = E + ((long)(b*SS + s0 + row0))*FF + seg*16;
    const uint32_t dA0 = sw128(row0, seg*2);
    const uint32_t dA1 = sw128(row0, seg*2 + 1);

    float acc[2][8][4];
#pragma unroll
    for (int mt = 0; mt < 2; mt++)
#pragma unroll
        for (int nt = 0; nt < 8; nt++)
#pragma unroll
            for (int e = 0; e < 4; e++) acc[mt][nt][e] = 0.0f;

#define B_FETCH(stp, k0)                                                         \
    do {                                                                         \
        _Pragma("unroll")                                                        \
        for (int j = 0; j < 8; j++) {                                            \
            int idx = tid + 256*j;                                               \
            int br = idx >> 3, bc = idx & 7;                                     \
            cp_async16((stp) + B_OFF + sw128(br, bc),                            \
                       g_Wh + (long)br*FF + (k0) + bc*8);                        \
        }                                                                        \
        CP_COMMIT();                                                             \
    } while (0)

#define A_STORE(stp, f0, f1, f2, f3)                                             \
    do {                                                                         \
        __half2 h0 = __floats2half2_rn((f0).x, (f0).y);                          \
        __half2 h1 = __floats2half2_rn((f0).z, (f0).w);                          \
        __half2 h2 = __floats2half2_rn((f1).x, (f1).y);                          \
        __half2 h3 = __floats2half2_rn((f1).z, (f1).w);                          \
        __half2 h4 = __floats2half2_rn((f2).x, (f2).y);                          \
        __half2 h5 = __floats2half2_rn((f2).z, (f2).w);                          \
        __half2 h6 = __floats2half2_rn((f3).x, (f3).y);                          \
        __half2 h7 = __floats2half2_rn((f3).z, (f3).w);                          \
        *(uint4*)((stp) + A_OFF + dA0) = make_uint4(                             \
            *(uint32_t*)&h0, *(uint32_t*)&h1, *(uint32_t*)&h2, *(uint32_t*)&h3); \
        *(uint4*)((stp) + A_OFF + dA1) = make_uint4(                             \
            *(uint32_t*)&h4, *(uint32_t*)&h5, *(uint32_t*)&h6, *(uint32_t*)&h7); \
    } while (0)

    {
        B_FETCH(sm, 0);
        float4 f0 = *(const float4*)(Ap);
        float4 f1 = *(const float4*)(Ap + 4);
        float4 f2 = *(const float4*)(Ap + 8);
        float4 f3 = *(const float4*)(Ap + 12);
        A_STORE(sm, f0, f1, f2, f3);
        CP_WAIT0();
        __syncthreads();
    }

    for (int c = 0; c < 8; c++) {
        const int cur = c & 1;
        char* stn = sm + (cur ^ 1)*STAGE;
        const uint32_t stcb = smb + cur*STAGE;

        float4 f0, f1, f2, f3;
        if (c < 7) {
            const int k1 = (c + 1)*64;
            B_FETCH(stn, k1);
            f0 = *(const float4*)(Ap + k1);
            f1 = *(const float4*)(Ap + k1 + 4);
            f2 = *(const float4*)(Ap + k1 + 8);
            f3 = *(const float4*)(Ap + k1 + 12);
        }

#pragma unroll
        for (int ks = 0; ks < 4; ks++) {
            uint32_t af[2][4];
#pragma unroll
            for (int mt = 0; mt < 2; mt++) {
                int r = wm*32 + mt*16 + (lane & 15);
                ldsm_x4(af[mt], stcb + A_OFF + sw128(r, ks*2 + (lane >> 4)));
            }
#pragma unroll
            for (int nb = 0; nb < 4; nb++) {
                int nr = wn*64 + nb*16 + ((lane >> 4) << 3) + (lane & 7);
                int cc = ks*2 + ((lane >> 3) & 1);
                uint32_t r4[4];
                ldsm_x4(r4, stcb + B_OFF + sw128(nr, cc));
                uint32_t b0[2] = { r4[0], r4[1] };
                uint32_t b1[2] = { r4[2], r4[3] };
#pragma unroll
                for (int mt = 0; mt < 2; mt++) {
                    mma_fp16(acc[mt][nb*2],     af[mt], b0);
                    mma_fp16(acc[mt][nb*2 + 1], af[mt], b1);
                }
            }
        }

        if (c < 7) {
            A_STORE(stn, f0, f1, f2, f3);
            CP_WAIT0();
        }
        __syncthreads();
    }

    // ---- epilogue 1: +qWh, tanh, dot v -> per-row scores in red[] ----
    float* red = (float*)(sm + SM_RED);   // [64 rows][4 n-warp groups]
#pragma unroll
    for (int mt = 0; mt < 2; mt++) {
        float pA = 0.0f, pB = 0.0f;
#pragma unroll
        for (int nt = 0; nt < 8; nt++) {
            int h0 = wn*64 + nt*8 + (lane & 3)*2;
            float q0 = sq[h0], q1 = sq[h0 + 1];
            float v0 = sv[h0], v1 = sv[h0 + 1];
            pA += v0*tanhf(acc[mt][nt][0] + q0) + v1*tanhf(acc[mt][nt][1] + q1);
            pB += v0*tanhf(acc[mt][nt][2] + q0) + v1*tanhf(acc[mt][nt][3] + q1);
        }
        pA += __shfl_xor_sync(0xffffffffu, pA, 1);
        pA += __shfl_xor_sync(0xffffffffu, pA, 2);
        pB += __shfl_xor_sync(0xffffffffu, pB, 1);
        pB += __shfl_xor_sync(0xffffffffu, pB, 2);
        if ((lane & 3) == 0) {
            int r = wm*32 + mt*16 + (lane >> 2);
            red[r*4 + wn]       = pA;
            red[(r + 8)*4 + wn] = pB;
        }
    }
    __syncthreads();

    // ---- epilogue 2: local softmax stats (m, w_r, S) ----
    float* mr  = (float*)(sm + SM_MR);
    float* swm = (float*)(sm + SM_SW);
    float s_loc = 0.0f;
    if (tid < 64)
        s_loc = red[tid*4] + red[tid*4+1] + red[tid*4+2] + red[tid*4+3];
    float mv = (tid < 64) ? s_loc : -3.0e38f;
#pragma unroll
    for (int o = 16; o; o >>= 1) mv = fmaxf(mv, __shfl_xor_sync(0xffffffffu, mv, o));
    if (tid < 64 && lane == 0) mr[warp] = mv;
    __syncthreads();
    const float mtile = fmaxf(mr[0], mr[1]);
    float wv = 0.0f;
    if (tid < 64) { wv = expf(s_loc - mtile); swm[tid] = wv; }
    float sv2 = (tid < 64) ? wv : 0.0f;
#pragma unroll
    for (int o = 16; o; o >>= 1) sv2 += __shfl_xor_sync(0xffffffffu, sv2, o);
    if (tid < 64 && lane == 0) mr[2 + warp] = sv2;
    __syncthreads();
    if (tid == 0)
        g_ms[b*NTILE + tile] = make_float2(mtile, mr[2] + mr[3]);

    // ---- epilogue 3: partial context = sum_r w_r * E[s0+r][f] (fp32) ----
    {
        float4* sctx = (float4*)(sm + SM_CTX);
        const int rg = tid >> 7;             // 0..1 (rows 0-31 / 32-63)
        const int fq = (tid & 127) * 4;
        const float* Eb = E + ((long)(b*SS + s0 + rg*32))*FF + fq;
        float4 a4 = make_float4(0.f, 0.f, 0.f, 0.f);
#pragma unroll 8
        for (int r = 0; r < 32; r++) {
            float w2 = swm[rg*32 + r];
            float4 e = *(const float4*)(Eb + (long)r*FF);
            a4.x += w2*e.x; a4.y += w2*e.y; a4.z += w2*e.z; a4.w += w2*e.w;
        }
        if (rg == 1) sctx[tid & 127] = a4;
        __syncthreads();
        if (rg == 0) {
            float4 o4 = sctx[tid];
            o4.x += a4.x; o4.y += a4.y; o4.z += a4.z; o4.w += a4.w;
            *(float4*)(&g_part[((long)tile*BB + b)*FF + fq]) = o4;
        }
    }
}

// ---- kernel 3: combine partials (max-corrected) + GRU + output proj ----
// 768 threads; batched loads + 4 independent accumulator chains everywhere.
__global__ void __launch_bounds__(768)
gru_kernel(const float* __restrict__ w_ih, const float* __restrict__ b_ih,
           const float* __restrict__ b_hh, const float* __restrict__ out_W,
           const float* __restrict__ out_b, float* __restrict__ out,
           int out_size)
{
    __shared__ __align__(16) float x[3*HH];
    __shared__ float g[3*HH];
    __shared__ float h[HH];
    __shared__ float fcs[NTILE];
    __shared__ float r4[8];
    __shared__ float sW[HH*OUTD];   // out_W staged (24.5 KB)
    const int b = blockIdx.x, tid = threadIdx.x;
    const int lane = tid & 31, warp = tid >> 5;

    // stage out_W while stats combine happens
    for (int i = tid; i < HH*OUTD; i += 768) sW[i] = out_W[i];

    // combine softmax stats across 64 tiles
    float2 ms = make_float2(-3.0e38f, 0.0f);
    if (tid < NTILE) ms = g_ms[b*NTILE + tid];
    float mv = ms.x;
#pragma unroll
    for (int o = 16; o; o >>= 1) mv = fmaxf(mv, __shfl_xor_sync(0xffffffffu, mv, o));
    if (tid < NTILE && lane == 0) r4[warp] = mv;
    __syncthreads();
    const float M = fmaxf(r4[0], r4[1]);
    float Sv = 0.0f;
    if (tid < NTILE) {
        float f_c = expf(ms.x - M);
        fcs[tid] = f_c;
        Sv = ms.y * f_c;
    }
#pragma unroll
    for (int o = 16; o; o >>= 1) Sv += __shfl_xor_sync(0xffffffffu, Sv, o);
    if (tid < NTILE && lane == 0) r4[2 + warp] = Sv;
    __syncthreads();
    const float inv_den = 1.0f / (r4[2] + r4[3]);

    // x[0:256] = embT (threads 512-767); x[256:768] = ctx (threads 0-511)
    if (tid < 512) {
        const float* gp = g_part + (long)b*FF + tid;
        float a0 = 0.f, a1 = 0.f, a2 = 0.f, a3 = 0.f;
#pragma unroll 2
        for (int c0 = 0; c0 < NTILE; c0 += 8) {
            float p[8];
#pragma unroll
            for (int i = 0; i < 8; i++) p[i] = gp[(long)(c0 + i)*BB*FF];
            a0 += p[0]*fcs[c0+0]; a1 += p[1]*fcs[c0+1];
            a2 += p[2]*fcs[c0+2]; a3 += p[3]*fcs[c0+3];
            a0 += p[4]*fcs[c0+4]; a1 += p[5]*fcs[c0+5];
            a2 += p[6]*fcs[c0+6]; a3 += p[7]*fcs[c0+7];
        }
        x[HH + tid] = ((a0 + a1) + (a2 + a3)) * inv_den;
    } else {
        x[tid - 512] = g_embT[b*HH + tid - 512];
    }
    __syncthreads();

    // gi = x @ w_ih + b_ih : thread per output; 16-wide load batches,
    // 4 independent FMA chains.
    {
        const float* wp = w_ih + tid;
        float a0 = 0.f, a1 = 0.f, a2 = 0.f, a3 = 0.f;
        for (int k0 = 0; k0 < 3*HH; k0 += 16) {
            float w[16];
#pragma unroll
            for (int i = 0; i < 16; i++) w[i] = wp[(k0 + i)*(3*HH)];
#pragma unroll
            for (int i = 0; i < 16; i += 4) {
                a0 += x[k0+i]   * w[i];
                a1 += x[k0+i+1] * w[i+1];
                a2 += x[k0+i+2] * w[i+2];
                a3 += x[k0+i+3] * w[i+3];
            }
        }
        g[tid] = ((a0 + a1) + (a2 + a3)) + b_ih[tid];
    }
    __syncthreads();

    // gates (h0 = 0 => gh = b_hh exactly)
    if (tid < HH) {
        const int j = tid;
        const float rg = sigmoidf_(g[j]        + b_hh[j]);
        const float zg = sigmoidf_(g[HH + j]   + b_hh[HH + j]);
        const float ng = tanhf   (g[2*HH + j]  + rg * b_hh[2*HH + j]);
        const float hv = (1.0f - zg) * ng;
        h[j] = hv;
        const int ho = BB*OUTD + b*HH + j;
        if (ho < out_size) out[ho] = hv;
    }
    __syncthreads();

    // output = h @ out_W + out_b : warp per output, lanes over k
    if (warp < OUTD) {
        float p = 0.0f;
#pragma unroll
        for (int i = 0; i < 8; i++) {
            int k = lane + i*32;
            p += h[k] * sW[k*OUTD + warp];
        }
#pragma unroll
        for (int o = 16; o; o >>= 1) p += __shfl_xor_sync(0xffffffffu, p, o);
        if (lane == 0) out[b*OUTD + warp] = p + out_b[warp];
    }
}

// ---------------- launch ----------------
extern "C" void kernel_launch(void* const* d_in, const int* in_sizes, int n_in,
                              void* d_out, int out_size)
{
    const int*   fc     = (const int*)  d_in[0];   // fut_ctxt (B,1)
    const int*   ft     = (const int*)  d_in[1];   // fut_temp (B,1)
    const float* E      = (const float*)d_in[2];   // encoder_outputs (B,S,2H)
    const float* emb_c  = (const float*)d_in[3];   // emb_ctxt (1000,H)
    const float* emb_t  = (const float*)d_in[4];   // emb_temp (1000,H)
    const float* attn_W = (const float*)d_in[5];   // (3H,H)
    const float* attn_b = (const float*)d_in[6];   // (H,)
    const float* v      = (const float*)d_in[7];   // (H,)
    const float* w_ih   = (const float*)d_in[8];   // (3H,3H)
    // d_in[9] = w_hh: unused since h0 == 0 (gh = b_hh exactly)
    const float* b_ih   = (const float*)d_in[10];  // (3H,)
    const float* b_hh   = (const float*)d_in[11];  // (3H,)
    const float* out_W  = (const float*)d_in[12];  // (H,OUT)
    const float* out_b  = (const float*)d_in[13];  // (OUT,)
    float* out = (float*)d_out;

    cudaFuncSetAttribute(scores_mma, cudaFuncAttributeMaxDynamicSharedMemorySize,
                         SMEM_SC);

    setup_prep<<<576, 256>>>(fc, ft, emb_c, emb_t, attn_W, attn_b);
    scores_mma<<<dim3(NTILE, BB), 256, SMEM_SC>>>(E, v);
    gru_kernel<<<BB, 768>>>(w_ih, b_ih, b_hh, out_W, out_b, out, out_size);
}

// round 16
// speedup vs baseline: 2.4976x; 1.0142x over previous
#include <cuda_runtime.h>
#include <cuda_fp16.h>
#include <cstdint>

#define BB   64
#define SS   4096
#define HH   256
#define FF   512      // 2*H
#define OUTD 24
#define NTILE 64      // s-tiles per batch (64 rows each)

// ---------------- scratch (static device globals; no allocs) ----------------
__device__ __align__(16) float g_qWh[BB*HH];      // hidden_q @ W_h + attn_b
__device__ __align__(16) float g_embT[BB*HH];     // gathered emb_temp
__device__ __align__(16) float g_part[NTILE*BB*FF]; // ctx partials per tile
__device__ __align__(16) float2 g_ms[BB*NTILE];   // (local max, local expsum)
__device__ __align__(16) __half g_Wh[HH*FF];      // W_e^T fp16 [n=256][k=512]

// ---------------- helpers ----------------
__device__ __forceinline__ uint32_t smem_u32(const void* p) {
    uint32_t a;
    asm("{ .reg .u64 t; cvta.to.shared.u64 t, %1; cvt.u32.u64 %0, t; }"
        : "=r"(a) : "l"(p));
    return a;
}
__device__ __forceinline__ void cp_async16(void* sm, const void* g) {
    unsigned s = (unsigned)__cvta_generic_to_shared(sm);
    asm volatile("cp.async.cg.shared.global [%0], [%1], 16;" :: "r"(s), "l"(g));
}
#define CP_COMMIT() asm volatile("cp.async.commit_group;")
#define CP_WAIT0()  asm volatile("cp.async.wait_group 0;")

__device__ __forceinline__ void ldsm_x4(uint32_t* r, uint32_t addr) {
    asm volatile("ldmatrix.sync.aligned.m8n8.x4.shared.b16 {%0,%1,%2,%3}, [%4];"
        : "=r"(r[0]), "=r"(r[1]), "=r"(r[2]), "=r"(r[3]) : "r"(addr));
}
__device__ __forceinline__ void mma_fp16(float* c, const uint32_t* a, const uint32_t* b) {
    asm volatile("mma.sync.aligned.m16n8k16.row.col.f32.f16.f16.f32 "
        "{%0,%1,%2,%3}, {%4,%5,%6,%7}, {%8,%9}, {%0,%1,%2,%3};"
        : "+f"(c[0]), "+f"(c[1]), "+f"(c[2]), "+f"(c[3])
        : "r"(a[0]), "r"(a[1]), "r"(a[2]), "r"(a[3]), "r"(b[0]), "r"(b[1]));
}
// 128B-row swizzle: 16B chunk c (0..7) of row r
__device__ __forceinline__ uint32_t sw128(int r, int c) {
    return (uint32_t)(r*128 + ((c ^ (r & 7)) << 4));
}
__device__ __forceinline__ float sigmoidf_(float x) { return 1.0f / (1.0f + expf(-x)); }

// ---- kernel 1: fused prep ----
// blocks 0-31:  W_e^T fp16 via smem tiles (coalesced read AND write)
// blocks 32-95: gathers + qWh with batched loads / 4 acc chains
__global__ void setup_prep(const int* __restrict__ fc, const int* __restrict__ ft,
                           const float* __restrict__ emb_c, const float* __restrict__ emb_t,
                           const float* __restrict__ attn_W, const float* __restrict__ attn_b)
{
    const int tid = threadIdx.x;
    if (blockIdx.x < 32) {
        // ---- transpose+convert one 64k x 64n tile of W_e ----
        __shared__ float t[64][65];
        const float* We = attn_W + HH*HH;              // [k=512][n=256]
        const int k0 = (blockIdx.x >> 2) * 64;
        const int n0 = (blockIdx.x & 3) * 64;
        const int nn_l = tid & 63;
#pragma unroll
        for (int i = 0; i < 16; i++) {
            int kk = i*4 + (tid >> 6);
            t[kk][nn_l] = We[(k0 + kk)*HH + n0 + nn_l];   // coalesced fp32 read
        }
        __syncthreads();
        const int nn = tid >> 2;                // 0..63
        const int ks = (tid & 3) * 16;          // 0,16,32,48
        __half2 buf[8];
#pragma unroll
        for (int j = 0; j < 8; j++)
            buf[j] = __floats2half2_rn(t[ks + j*2][nn], t[ks + j*2 + 1][nn]);
        uint4* dst = (uint4*)(&g_Wh[(n0 + nn)*FF + k0 + ks]);   // 32B contiguous
        dst[0] = make_uint4(*(uint32_t*)&buf[0], *(uint32_t*)&buf[1],
                            *(uint32_t*)&buf[2], *(uint32_t*)&buf[3]);
        dst[1] = make_uint4(*(uint32_t*)&buf[4], *(uint32_t*)&buf[5],
                            *(uint32_t*)&buf[6], *(uint32_t*)&buf[7]);
    } else {
        // ---- gathers + qWh = emb_ctxt[idx] @ W_h + attn_b ----
        __shared__ float q[HH];
        int b = blockIdx.x - 32;
        int ci = fc[b], ti = ft[b];
        q[tid] = emb_c[ci*HH + tid];
        g_embT[b*HH + tid] = emb_t[ti*HH + tid];
        __syncthreads();
        const float* wp = attn_W + tid;
        float a0 = 0.f, a1 = 0.f, a2 = 0.f, a3 = 0.f;
        for (int k0 = 0; k0 < HH; k0 += 8) {
            float w[8];
#pragma unroll
            for (int i = 0; i < 8; i++) w[i] = wp[(k0 + i)*HH];   // coalesced
            a0 += q[k0+0]*w[0]; a1 += q[k0+1]*w[1];
            a2 += q[k0+2]*w[2]; a3 += q[k0+3]*w[3];
            a0 += q[k0+4]*w[4]; a1 += q[k0+5]*w[5];
            a2 += q[k0+6]*w[6]; a3 += q[k0+7]*w[7];
        }
        g_qWh[b*HH + tid] = ((a0 + a1) + (a2 + a3)) + attn_b[tid];
    }
}

// ---- kernel 2: fp16 mma.sync scores GEMM + fused softmax-partial + ctx ----
// (unchanged — at the legacy-HMMA issue ceiling)
#define STAGE   40960                // A 8KB + B 32KB
#define A_OFF   0
#define B_OFF   8192
#define SM_QW   (2*STAGE)
#define SM_V    (SM_QW + 1024)
#define SM_RED  (SM_V + 1024)
#define SM_SW   (SM_RED + 1024)
#define SM_MR   (SM_SW + 256)
#define SM_CTX  (SM_MR + 128)
#define SMEM_SC (SM_CTX + 2048)

__global__ void __launch_bounds__(256, 2)
scores_mma(const float* __restrict__ E, const float* __restrict__ v)
{
    extern __shared__ char sm[];
    const uint32_t smb = smem_u32(sm);
    const int tid  = threadIdx.x;
    const int lane = tid & 31, warp = tid >> 5;
    const int wm = warp >> 2, wn = warp & 3;       // 2 x 4 warp grid
    const int tile = blockIdx.x;
    const int s0 = tile * 64;
    const int b  = blockIdx.y;

    float* sq = (float*)(sm + SM_QW);
    float* sv = (float*)(sm + SM_V);
    sq[tid] = g_qWh[b*HH + tid];
    sv[tid] = v[tid];

    const int seg  = tid & 3;
    const int row0 = tid >> 2;
    const float* Ap = E + ((long)(b*SS + s0 + row0))*FF + seg*16;
    const uint32_t dA0 = sw128(row0, seg*2);
    const uint32_t dA1 = sw128(row0, seg*2 + 1);

    float acc[2][8][4];
#pragma unroll
    for (int mt = 0; mt < 2; mt++)
#pragma unroll
        for (int nt = 0; nt < 8; nt++)
#pragma unroll
            for (int e = 0; e < 4; e++) acc[mt][nt][e] = 0.0f;

#define B_FETCH(stp, k0)                                                         \
    do {                                                                         \
        _Pragma("unroll")                                                        \
        for (int j = 0; j < 8; j++) {                                            \
            int idx = tid + 256*j;                                               \
            int br = idx >> 3, bc = idx & 7;                                     \
            cp_async16((stp) + B_OFF + sw128(br, bc),                            \
                       g_Wh + (long)br*FF + (k0) + bc*8);                        \
        }                                                                        \
        CP_COMMIT();                                                             \
    } while (0)

#define A_STORE(stp, f0, f1, f2, f3)                                             \
    do {                                                                         \
        __half2 h0 = __floats2half2_rn((f0).x, (f0).y);                          \
        __half2 h1 = __floats2half2_rn((f0).z, (f0).w);                          \
        __half2 h2 = __floats2half2_rn((f1).x, (f1).y);                          \
        __half2 h3 = __floats2half2_rn((f1).z, (f1).w);                          \
        __half2 h4 = __floats2half2_rn((f2).x, (f2).y);                          \
        __half2 h5 = __floats2half2_rn((f2).z, (f2).w);                          \
        __half2 h6 = __floats2half2_rn((f3).x, (f3).y);                          \
        __half2 h7 = __floats2half2_rn((f3).z, (f3).w);                          \
        *(uint4*)((stp) + A_OFF + dA0) = make_uint4(                             \
            *(uint32_t*)&h0, *(uint32_t*)&h1, *(uint32_t*)&h2, *(uint32_t*)&h3); \
        *(uint4*)((stp) + A_OFF + dA1) = make_uint4(                             \
            *(uint32_t*)&h4, *(uint32_t*)&h5, *(uint32_t*)&h6, *(uint32_t*)&h7); \
    } while (0)

    {
        B_FETCH(sm, 0);
        float4 f0 = *(const float4*)(Ap);
        float4 f1 = *(const float4*)(Ap + 4);
        float4 f2 = *(const float4*)(Ap + 8);
        float4 f3 = *(const float4*)(Ap + 12);
        A_STORE(sm, f0, f1, f2, f3);
        CP_WAIT0();
        __syncthreads();
    }

    for (int c = 0; c < 8; c++) {
        const int cur = c & 1;
        char* stn = sm + (cur ^ 1)*STAGE;
        const uint32_t stcb = smb + cur*STAGE;

        float4 f0, f1, f2, f3;
        if (c < 7) {
            const int k1 = (c + 1)*64;
            B_FETCH(stn, k1);
            f0 = *(const float4*)(Ap + k1);
            f1 = *(const float4*)(Ap + k1 + 4);
            f2 = *(const float4*)(Ap + k1 + 8);
            f3 = *(const float4*)(Ap + k1 + 12);
        }

#pragma unroll
        for (int ks = 0; ks < 4; ks++) {
            uint32_t af[2][4];
#pragma unroll
            for (int mt = 0; mt < 2; mt++) {
                int r = wm*32 + mt*16 + (lane & 15);
                ldsm_x4(af[mt], stcb + A_OFF + sw128(r, ks*2 + (lane >> 4)));
            }
#pragma unroll
            for (int nb = 0; nb < 4; nb++) {
                int nr = wn*64 + nb*16 + ((lane >> 4) << 3) + (lane & 7);
                int cc = ks*2 + ((lane >> 3) & 1);
                uint32_t r4[4];
                ldsm_x4(r4, stcb + B_OFF + sw128(nr, cc));
                uint32_t b0[2] = { r4[0], r4[1] };
                uint32_t b1[2] = { r4[2], r4[3] };
#pragma unroll
                for (int mt = 0; mt < 2; mt++) {
                    mma_fp16(acc[mt][nb*2],     af[mt], b0);
                    mma_fp16(acc[mt][nb*2 + 1], af[mt], b1);
                }
            }
        }

        if (c < 7) {
            A_STORE(stn, f0, f1, f2, f3);
            CP_WAIT0();
        }
        __syncthreads();
    }

    // ---- epilogue 1: +qWh, tanh, dot v -> per-row scores in red[] ----
    float* red = (float*)(sm + SM_RED);   // [64 rows][4 n-warp groups]
#pragma unroll
    for (int mt = 0; mt < 2; mt++) {
        float pA = 0.0f, pB = 0.0f;
#pragma unroll
        for (int nt = 0; nt < 8; nt++) {
            int h0 = wn*64 + nt*8 + (lane & 3)*2;
            float q0 = sq[h0], q1 = sq[h0 + 1];
            float v0 = sv[h0], v1 = sv[h0 + 1];
            pA += v0*tanhf(acc[mt][nt][0] + q0) + v1*tanhf(acc[mt][nt][1] + q1);
            pB += v0*tanhf(acc[mt][nt][2] + q0) + v1*tanhf(acc[mt][nt][3] + q1);
        }
        pA += __shfl_xor_sync(0xffffffffu, pA, 1);
        pA += __shfl_xor_sync(0xffffffffu, pA, 2);
        pB += __shfl_xor_sync(0xffffffffu, pB, 1);
        pB += __shfl_xor_sync(0xffffffffu, pB, 2);
        if ((lane & 3) == 0) {
            int r = wm*32 + mt*16 + (lane >> 2);
            red[r*4 + wn]       = pA;
            red[(r + 8)*4 + wn] = pB;
        }
    }
    __syncthreads();

    // ---- epilogue 2: local softmax stats (m, w_r, S) ----
    float* mr  = (float*)(sm + SM_MR);
    float* swm = (float*)(sm + SM_SW);
    float s_loc = 0.0f;
    if (tid < 64)
        s_loc = red[tid*4] + red[tid*4+1] + red[tid*4+2] + red[tid*4+3];
    float mv = (tid < 64) ? s_loc : -3.0e38f;
#pragma unroll
    for (int o = 16; o; o >>= 1) mv = fmaxf(mv, __shfl_xor_sync(0xffffffffu, mv, o));
    if (tid < 64 && lane == 0) mr[warp] = mv;
    __syncthreads();
    const float mtile = fmaxf(mr[0], mr[1]);
    float wv = 0.0f;
    if (tid < 64) { wv = expf(s_loc - mtile); swm[tid] = wv; }
    float sv2 = (tid < 64) ? wv : 0.0f;
#pragma unroll
    for (int o = 16; o; o >>= 1) sv2 += __shfl_xor_sync(0xffffffffu, sv2, o);
    if (tid < 64 && lane == 0) mr[2 + warp] = sv2;
    __syncthreads();
    if (tid == 0)
        g_ms[b*NTILE + tile] = make_float2(mtile, mr[2] + mr[3]);

    // ---- epilogue 3: partial context = sum_r w_r * E[s0+r][f] (fp32) ----
    {
        float4* sctx = (float4*)(sm + SM_CTX);
        const int rg = tid >> 7;             // 0..1 (rows 0-31 / 32-63)
        const int fq = (tid & 127) * 4;
        const float* Eb = E + ((long)(b*SS + s0 + rg*32))*FF + fq;
        float4 a4 = make_float4(0.f, 0.f, 0.f, 0.f);
#pragma unroll 8
        for (int r = 0; r < 32; r++) {
            float w2 = swm[rg*32 + r];
            float4 e = *(const float4*)(Eb + (long)r*FF);
            a4.x += w2*e.x; a4.y += w2*e.y; a4.z += w2*e.z; a4.w += w2*e.w;
        }
        if (rg == 1) sctx[tid & 127] = a4;
        __syncthreads();
        if (rg == 0) {
            float4 o4 = sctx[tid];
            o4.x += a4.x; o4.y += a4.y; o4.z += a4.z; o4.w += a4.w;
            *(float4*)(&g_part[((long)tile*BB + b)*FF + fq]) = o4;
        }
    }
}

// ---- kernel 3: combine partials (max-corrected) + GRU + output proj ----
// (unchanged from R15)
__global__ void __launch_bounds__(768)
gru_kernel(const float* __restrict__ w_ih, const float* __restrict__ b_ih,
           const float* __restrict__ b_hh, const float* __restrict__ out_W,
           const float* __restrict__ out_b, float* __restrict__ out,
           int out_size)
{
    __shared__ __align__(16) float x[3*HH];
    __shared__ float g[3*HH];
    __shared__ float h[HH];
    __shared__ float fcs[NTILE];
    __shared__ float r4[8];
    __shared__ float sW[HH*OUTD];   // out_W staged (24.5 KB)
    const int b = blockIdx.x, tid = threadIdx.x;
    const int lane = tid & 31, warp = tid >> 5;

    for (int i = tid; i < HH*OUTD; i += 768) sW[i] = out_W[i];

    float2 ms = make_float2(-3.0e38f, 0.0f);
    if (tid < NTILE) ms = g_ms[b*NTILE + tid];
    float mv = ms.x;
#pragma unroll
    for (int o = 16; o; o >>= 1) mv = fmaxf(mv, __shfl_xor_sync(0xffffffffu, mv, o));
    if (tid < NTILE && lane == 0) r4[warp] = mv;
    __syncthreads();
    const float M = fmaxf(r4[0], r4[1]);
    float Sv = 0.0f;
    if (tid < NTILE) {
        float f_c = expf(ms.x - M);
        fcs[tid] = f_c;
        Sv = ms.y * f_c;
    }
#pragma unroll
    for (int o = 16; o; o >>= 1) Sv += __shfl_xor_sync(0xffffffffu, Sv, o);
    if (tid < NTILE && lane == 0) r4[2 + warp] = Sv;
    __syncthreads();
    const float inv_den = 1.0f / (r4[2] + r4[3]);

    if (tid < 512) {
        const float* gp = g_part + (long)b*FF + tid;
        float a0 = 0.f, a1 = 0.f, a2 = 0.f, a3 = 0.f;
#pragma unroll 2
        for (int c0 = 0; c0 < NTILE; c0 += 8) {
            float p[8];
#pragma unroll
            for (int i = 0; i < 8; i++) p[i] = gp[(long)(c0 + i)*BB*FF];
            a0 += p[0]*fcs[c0+0]; a1 += p[1]*fcs[c0+1];
            a2 += p[2]*fcs[c0+2]; a3 += p[3]*fcs[c0+3];
            a0 += p[4]*fcs[c0+4]; a1 += p[5]*fcs[c0+5];
            a2 += p[6]*fcs[c0+6]; a3 += p[7]*fcs[c0+7];
        }
        x[HH + tid] = ((a0 + a1) + (a2 + a3)) * inv_den;
    } else {
        x[tid - 512] = g_embT[b*HH + tid - 512];
    }
    __syncthreads();

    {
        const float* wp = w_ih + tid;
        float a0 = 0.f, a1 = 0.f, a2 = 0.f, a3 = 0.f;
        for (int k0 = 0; k0 < 3*HH; k0 += 16) {
            float w[16];
#pragma unroll
            for (int i = 0; i < 16; i++) w[i] = wp[(k0 + i)*(3*HH)];
#pragma unroll
            for (int i = 0; i < 16; i += 4) {
                a0 += x[k0+i]   * w[i];
                a1 += x[k0+i+1] * w[i+1];
                a2 += x[k0+i+2] * w[i+2];
                a3 += x[k0+i+3] * w[i+3];
            }
        }
        g[tid] = ((a0 + a1) + (a2 + a3)) + b_ih[tid];
    }
    __syncthreads();

    if (tid < HH) {
        const int j = tid;
        const float rg = sigmoidf_(g[j]        + b_hh[j]);
        const float zg = sigmoidf_(g[HH + j]   + b_hh[HH + j]);
        const float ng = tanhf   (g[2*HH + j]  + rg * b_hh[2*HH + j]);
        const float hv = (1.0f - zg) * ng;
        h[j] = hv;
        const int ho = BB*OUTD + b*HH + j;
        if (ho < out_size) out[ho] = hv;
    }
    __syncthreads();

    if (warp < OUTD) {
        float p = 0.0f;
#pragma unroll
        for (int i = 0; i < 8; i++) {
            int k = lane + i*32;
            p += h[k] * sW[k*OUTD + warp];
        }
#pragma unroll
        for (int o = 16; o; o >>= 1) p += __shfl_xor_sync(0xffffffffu, p, o);
        if (lane == 0) out[b*OUTD + warp] = p + out_b[warp];
    }
}

// ---------------- launch ----------------
extern "C" void kernel_launch(void* const* d_in, const int* in_sizes, int n_in,
                              void* d_out, int out_size)
{
    const int*   fc     = (const int*)  d_in[0];   // fut_ctxt (B,1)
    const int*   ft     = (const int*)  d_in[1];   // fut_temp (B,1)
    const float* E      = (const float*)d_in[2];   // encoder_outputs (B,S,2H)
    const float* emb_c  = (const float*)d_in[3];   // emb_ctxt (1000,H)
    const float* emb_t  = (const float*)d_in[4];   // emb_temp (1000,H)
    const float* attn_W = (const float*)d_in[5];   // (3H,H)
    const float* attn_b = (const float*)d_in[6];   // (H,)
    const float* v      = (const float*)d_in[7];   // (H,)
    const float* w_ih   = (const float*)d_in[8];   // (3H,3H)
    // d_in[9] = w_hh: unused since h0 == 0 (gh = b_hh exactly)
    const float* b_ih   = (const float*)d_in[10];  // (3H,)
    const float* b_hh   = (const float*)d_in[11];  // (3H,)
    const float* out_W  = (const float*)d_in[12];  // (H,OUT)
    const float* out_b  = (const float*)d_in[13];  // (OUT,)
    float* out = (float*)d_out;

    cudaFuncSetAttribute(scores_mma, cudaFuncAttributeMaxDynamicSharedMemorySize,
                         SMEM_SC);

    setup_prep<<<32 + BB, 256>>>(fc, ft, emb_c, emb_t, attn_W, attn_b);
    scores_mma<<<dim3(NTILE, BB), 256, SMEM_SC>>>(E, v);
    gru_kernel<<<BB, 768>>>(w_ih, b_ih, b_hh, out_W, out_b, out, out_size);
}

// round 17
// speedup vs baseline: 2.5249x; 1.0109x over previous
#include <cuda_runtime.h>
#include <cuda_fp16.h>
#include <cstdint>

#define BB   64
#define SS   4096
#define HH   256
#define FF   512      // 2*H
#define OUTD 24
#define NTILE 64      // s-tiles per batch (64 rows each)

// ---------------- scratch (static device globals; no allocs) ----------------
__device__ __align__(16) float g_qWh2[2*BB*HH];   // qWh k-half partials
__device__ __align__(16) float g_embT[BB*HH];     // gathered emb_temp
__device__ __align__(16) float g_part[NTILE*BB*FF]; // ctx partials per tile
__device__ __align__(16) float2 g_ms[BB*NTILE];   // (local max, local expsum)
__device__ __align__(16) __half g_Wh[HH*FF];      // W_e^T fp16 [n=256][k=512]

// ---------------- helpers ----------------
__device__ __forceinline__ uint32_t smem_u32(const void* p) {
    uint32_t a;
    asm("{ .reg .u64 t; cvta.to.shared.u64 t, %1; cvt.u32.u64 %0, t; }"
        : "=r"(a) : "l"(p));
    return a;
}
__device__ __forceinline__ void cp_async16(void* sm, const void* g) {
    unsigned s = (unsigned)__cvta_generic_to_shared(sm);
    asm volatile("cp.async.cg.shared.global [%0], [%1], 16;" :: "r"(s), "l"(g));
}
#define CP_COMMIT() asm volatile("cp.async.commit_group;")
#define CP_WAIT0()  asm volatile("cp.async.wait_group 0;")

__device__ __forceinline__ void ldsm_x4(uint32_t* r, uint32_t addr) {
    asm volatile("ldmatrix.sync.aligned.m8n8.x4.shared.b16 {%0,%1,%2,%3}, [%4];"
        : "=r"(r[0]), "=r"(r[1]), "=r"(r[2]), "=r"(r[3]) : "r"(addr));
}
__device__ __forceinline__ void mma_fp16(float* c, const uint32_t* a, const uint32_t* b) {
    asm volatile("mma.sync.aligned.m16n8k16.row.col.f32.f16.f16.f32 "
        "{%0,%1,%2,%3}, {%4,%5,%6,%7}, {%8,%9}, {%0,%1,%2,%3};"
        : "+f"(c[0]), "+f"(c[1]), "+f"(c[2]), "+f"(c[3])
        : "r"(a[0]), "r"(a[1]), "r"(a[2]), "r"(a[3]), "r"(b[0]), "r"(b[1]));
}
// 128B-row swizzle: 16B chunk c (0..7) of row r
__device__ __forceinline__ uint32_t sw128(int r, int c) {
    return (uint32_t)(r*128 + ((c ^ (r & 7)) << 4));
}
__device__ __forceinline__ float sigmoidf_(float x) { return 1.0f / (1.0f + expf(-x)); }

// ---- kernel 1: fused prep ----
// blocks 0-31:    W_e^T fp16 via smem tiles (coalesced read AND write)
// blocks 32-159:  qWh k-half partials (2 blocks per batch) + gathers
__global__ void setup_prep(const int* __restrict__ fc, const int* __restrict__ ft,
                           const float* __restrict__ emb_c, const float* __restrict__ emb_t,
                           const float* __restrict__ attn_W, const float* __restrict__ attn_b)
{
    const int tid = threadIdx.x;
    if (blockIdx.x < 32) {
        // ---- transpose+convert one 64k x 64n tile of W_e ----
        __shared__ float t[64][65];
        const float* We = attn_W + HH*HH;              // [k=512][n=256]
        const int k0 = (blockIdx.x >> 2) * 64;
        const int n0 = (blockIdx.x & 3) * 64;
        const int nn_l = tid & 63;
#pragma unroll
        for (int i = 0; i < 16; i++) {
            int kk = i*4 + (tid >> 6);
            t[kk][nn_l] = We[(k0 + kk)*HH + n0 + nn_l];   // coalesced fp32 read
        }
        __syncthreads();
        const int nn = tid >> 2;                // 0..63
        const int ks = (tid & 3) * 16;          // 0,16,32,48
        __half2 buf[8];
#pragma unroll
        for (int j = 0; j < 8; j++)
            buf[j] = __floats2half2_rn(t[ks + j*2][nn], t[ks + j*2 + 1][nn]);
        uint4* dst = (uint4*)(&g_Wh[(n0 + nn)*FF + k0 + ks]);   // 32B contiguous
        dst[0] = make_uint4(*(uint32_t*)&buf[0], *(uint32_t*)&buf[1],
                            *(uint32_t*)&buf[2], *(uint32_t*)&buf[3]);
        dst[1] = make_uint4(*(uint32_t*)&buf[4], *(uint32_t*)&buf[5],
                            *(uint32_t*)&buf[6], *(uint32_t*)&buf[7]);
    } else {
        // ---- qWh partial: half h of k for batch b ----
        __shared__ float q[128];
        const int idx = blockIdx.x - 32;
        const int b = idx >> 1, hf = idx & 1;
        const int ci = fc[b];
        if (tid < 128) q[tid] = emb_c[ci*HH + hf*128 + tid];
        if (hf == 0) {
            int ti = ft[b];
            g_embT[b*HH + tid] = emb_t[ti*HH + tid];     // gather once per b
        }
        __syncthreads();
        const float* wp = attn_W + (hf*128)*HH + tid;
        float a0 = 0.f, a1 = 0.f, a2 = 0.f, a3 = 0.f;
        for (int k0 = 0; k0 < 128; k0 += 16) {
            float w[16];
#pragma unroll
            for (int i = 0; i < 16; i++) w[i] = wp[(k0 + i)*HH];   // coalesced
#pragma unroll
            for (int i = 0; i < 16; i += 4) {
                a0 += q[k0+i]   * w[i];
                a1 += q[k0+i+1] * w[i+1];
                a2 += q[k0+i+2] * w[i+2];
                a3 += q[k0+i+3] * w[i+3];
            }
        }
        float r = ((a0 + a1) + (a2 + a3));
        if (hf == 0) r += attn_b[tid];
        g_qWh2[hf*BB*HH + b*HH + tid] = r;
    }
}

// ---- kernel 2: fp16 mma.sync scores GEMM + fused softmax-partial + ctx ----
// (GEMM identical to R13-R16 — at the legacy-HMMA issue ceiling)
#define STAGE   40960                // A 8KB + B 32KB
#define A_OFF   0
#define B_OFF   8192
#define SM_QW   (2*STAGE)
#define SM_V    (SM_QW + 1024)
#define SM_RED  (SM_V + 1024)
#define SM_SW   (SM_RED + 1024)
#define SM_MR   (SM_SW + 256)
#define SM_CTX  (SM_MR + 128)
#define SMEM_SC (SM_CTX + 2048)

__global__ void __launch_bounds__(256, 2)
scores_mma(const float* __restrict__ E, const float* __restrict__ v)
{
    extern __shared__ char sm[];
    const uint32_t smb = smem_u32(sm);
    const int tid  = threadIdx.x;
    const int lane = tid & 31, warp = tid >> 5;
    const int wm = warp >> 2, wn = warp & 3;       // 2 x 4 warp grid
    const int tile = blockIdx.x;
    const int s0 = tile * 64;
    const int b  = blockIdx.y;

    float* sq = (float*)(sm + SM_QW);
    float* sv = (float*)(sm + SM_V);
    sq[tid] = g_qWh2[b*HH + tid] + g_qWh2[BB*HH + b*HH + tid];
    sv[tid] = v[tid];

    const int seg  = tid & 3;
    const int row0 = tid >> 2;
    const float* Ap = E + ((long)(b*SS + s0 + row0))*FF + seg*16;
    const uint32_t dA0 = sw128(row0, seg*2);
    const uint32_t dA1 = sw128(row0, seg*2 + 1);

    float acc[2][8][4];
#pragma unroll
    for (int mt = 0; mt < 2; mt++)
#pragma unroll
        for (int nt = 0; nt < 8; nt++)
#pragma unroll
            for (int e = 0; e < 4; e++) acc[mt][nt][e] = 0.0f;

#define B_FETCH(stp, k0)                                                         \
    do {                                                                         \
        _Pragma("unroll")                                                        \
        for (int j = 0; j < 8; j++) {                                            \
            int idx = tid + 256*j;                                               \
            int br = idx >> 3, bc = idx & 7;                                     \
            cp_async16((stp) + B_OFF + sw128(br, bc),                            \
                       g_Wh + (long)br*FF + (k0) + bc*8);                        \
        }                                                                        \
        CP_COMMIT();                                                             \
    } while (0)

#define A_STORE(stp, f0, f1, f2, f3)                                             \
    do {                                                                         \
        __half2 h0 = __floats2half2_rn((f0).x, (f0).y);                          \
        __half2 h1 = __floats2half2_rn((f0).z, (f0).w);                          \
        __half2 h2 = __floats2half2_rn((f1).x, (f1).y);                          \
        __half2 h3 = __floats2half2_rn((f1).z, (f1).w);                          \
        __half2 h4 = __floats2half2_rn((f2).x, (f2).y);                          \
        __half2 h5 = __floats2half2_rn((f2).z, (f2).w);                          \
        __half2 h6 = __floats2half2_rn((f3).x, (f3).y);                          \
        __half2 h7 = __floats2half2_rn((f3).z, (f3).w);                          \
        *(uint4*)((stp) + A_OFF + dA0) = make_uint4(                             \
            *(uint32_t*)&h0, *(uint32_t*)&h1, *(uint32_t*)&h2, *(uint32_t*)&h3); \
        *(uint4*)((stp) + A_OFF + dA1) = make_uint4(                             \
            *(uint32_t*)&h4, *(uint32_t*)&h5, *(uint32_t*)&h6, *(uint32_t*)&h7); \
    } while (0)

    {
        B_FETCH(sm, 0);
        float4 f0 = *(const float4*)(Ap);
        float4 f1 = *(const float4*)(Ap + 4);
        float4 f2 = *(const float4*)(Ap + 8);
        float4 f3 = *(const float4*)(Ap + 12);
        A_STORE(sm, f0, f1, f2, f3);
        CP_WAIT0();
        __syncthreads();
    }

    for (int c = 0; c < 8; c++) {
        const int cur = c & 1;
        char* stn = sm + (cur ^ 1)*STAGE;
        const uint32_t stcb = smb + cur*STAGE;

        float4 f0, f1, f2, f3;
        if (c < 7) {
            const int k1 = (c + 1)*64;
            B_FETCH(stn, k1);
            f0 = *(const float4*)(Ap + k1);
            f1 = *(const float4*)(Ap + k1 + 4);
            f2 = *(const float4*)(Ap + k1 + 8);
            f3 = *(const float4*)(Ap + k1 + 12);
        }

#pragma unroll
        for (int ks = 0; ks < 4; ks++) {
            uint32_t af[2][4];
#pragma unroll
            for (int mt = 0; mt < 2; mt++) {
                int r = wm*32 + mt*16 + (lane & 15);
                ldsm_x4(af[mt], stcb + A_OFF + sw128(r, ks*2 + (lane >> 4)));
            }
#pragma unroll
            for (int nb = 0; nb < 4; nb++) {
                int nr = wn*64 + nb*16 + ((lane >> 4) << 3) + (lane & 7);
                int cc = ks*2 + ((lane >> 3) & 1);
                uint32_t r4[4];
                ldsm_x4(r4, stcb + B_OFF + sw128(nr, cc));
                uint32_t b0[2] = { r4[0], r4[1] };
                uint32_t b1[2] = { r4[2], r4[3] };
#pragma unroll
                for (int mt = 0; mt < 2; mt++) {
                    mma_fp16(acc[mt][nb*2],     af[mt], b0);
                    mma_fp16(acc[mt][nb*2 + 1], af[mt], b1);
                }
            }
        }

        if (c < 7) {
            A_STORE(stn, f0, f1, f2, f3);
            CP_WAIT0();
        }
        __syncthreads();
    }

    // ---- epilogue 1: +qWh, tanh, dot v -> per-row scores in red[] ----
    float* red = (float*)(sm + SM_RED);   // [64 rows][4 n-warp groups]
#pragma unroll
    for (int mt = 0; mt < 2; mt++) {
        float pA = 0.0f, pB = 0.0f;
#pragma unroll
        for (int nt = 0; nt < 8; nt++) {
            int h0 = wn*64 + nt*8 + (lane & 3)*2;
            float q0 = sq[h0], q1 = sq[h0 + 1];
            float v0 = sv[h0], v1 = sv[h0 + 1];
            pA += v0*tanhf(acc[mt][nt][0] + q0) + v1*tanhf(acc[mt][nt][1] + q1);
            pB += v0*tanhf(acc[mt][nt][2] + q0) + v1*tanhf(acc[mt][nt][3] + q1);
        }
        pA += __shfl_xor_sync(0xffffffffu, pA, 1);
        pA += __shfl_xor_sync(0xffffffffu, pA, 2);
        pB += __shfl_xor_sync(0xffffffffu, pB, 1);
        pB += __shfl_xor_sync(0xffffffffu, pB, 2);
        if ((lane & 3) == 0) {
            int r = wm*32 + mt*16 + (lane >> 2);
            red[r*4 + wn]       = pA;
            red[(r + 8)*4 + wn] = pB;
        }
    }
    __syncthreads();

    // ---- epilogue 2: local softmax stats (m, w_r, S) ----
    float* mr  = (float*)(sm + SM_MR);
    float* swm = (float*)(sm + SM_SW);
    float s_loc = 0.0f;
    if (tid < 64)
        s_loc = red[tid*4] + red[tid*4+1] + red[tid*4+2] + red[tid*4+3];
    float mv = (tid < 64) ? s_loc : -3.0e38f;
#pragma unroll
    for (int o = 16; o; o >>= 1) mv = fmaxf(mv, __shfl_xor_sync(0xffffffffu, mv, o));
    if (tid < 64 && lane == 0) mr[warp] = mv;
    __syncthreads();
    const float mtile = fmaxf(mr[0], mr[1]);
    float wv = 0.0f;
    if (tid < 64) { wv = expf(s_loc - mtile); swm[tid] = wv; }
    float sv2 = (tid < 64) ? wv : 0.0f;
#pragma unroll
    for (int o = 16; o; o >>= 1) sv2 += __shfl_xor_sync(0xffffffffu, sv2, o);
    if (tid < 64 && lane == 0) mr[2 + warp] = sv2;
    __syncthreads();
    if (tid == 0)
        g_ms[b*NTILE + tile] = make_float2(mtile, mr[2] + mr[3]);

    // ---- epilogue 3: partial context = sum_r w_r * E[s0+r][f] (fp32) ----
    {
        float4* sctx = (float4*)(sm + SM_CTX);
        const int rg = tid >> 7;             // 0..1 (rows 0-31 / 32-63)
        const int fq = (tid & 127) * 4;
        const float* Eb = E + ((long)(b*SS + s0 + rg*32))*FF + fq;
        float4 a4 = make_float4(0.f, 0.f, 0.f, 0.f);
#pragma unroll 8
        for (int r = 0; r < 32; r++) {
            float w2 = swm[rg*32 + r];
            float4 e = *(const float4*)(Eb + (long)r*FF);
            a4.x += w2*e.x; a4.y += w2*e.y; a4.z += w2*e.z; a4.w += w2*e.w;
        }
        if (rg == 1) sctx[tid & 127] = a4;
        __syncthreads();
        if (rg == 0) {
            float4 o4 = sctx[tid];
            o4.x += a4.x; o4.y += a4.y; o4.z += a4.z; o4.w += a4.w;
            *(float4*)(&g_part[((long)tile*BB + b)*FF + fq]) = o4;
        }
    }
}

// ---- kernel 3: combine partials (max-corrected) + GRU + output proj ----
__global__ void __launch_bounds__(768)
gru_kernel(const float* __restrict__ w_ih, const float* __restrict__ b_ih,
           const float* __restrict__ b_hh, const float* __restrict__ out_W,
           const float* __restrict__ out_b, float* __restrict__ out,
           int out_size)
{
    __shared__ __align__(16) float x[3*HH];
    __shared__ float g[3*HH];
    __shared__ float h[HH];
    __shared__ float fcs[NTILE];
    __shared__ float r4[8];
    __shared__ float sW[HH*OUTD];   // out_W staged (24.5 KB)
    const int b = blockIdx.x, tid = threadIdx.x;
    const int lane = tid & 31, warp = tid >> 5;

    for (int i = tid; i < HH*OUTD; i += 768) sW[i] = out_W[i];

    float2 ms = make_float2(-3.0e38f, 0.0f);
    if (tid < NTILE) ms = g_ms[b*NTILE + tid];
    float mv = ms.x;
#pragma unroll
    for (int o = 16; o; o >>= 1) mv = fmaxf(mv, __shfl_xor_sync(0xffffffffu, mv, o));
    if (tid < NTILE && lane == 0) r4[warp] = mv;
    __syncthreads();
    const float M = fmaxf(r4[0], r4[1]);
    float Sv = 0.0f;
    if (tid < NTILE) {
        float f_c = expf(ms.x - M);
        fcs[tid] = f_c;
        Sv = ms.y * f_c;
    }
#pragma unroll
    for (int o = 16; o; o >>= 1) Sv += __shfl_xor_sync(0xffffffffu, Sv, o);
    if (tid < NTILE && lane == 0) r4[2 + warp] = Sv;
    __syncthreads();
    const float inv_den = 1.0f / (r4[2] + r4[3]);

    if (tid < 512) {
        const float* gp = g_part + (long)b*FF + tid;
        float a0 = 0.f, a1 = 0.f, a2 = 0.f, a3 = 0.f;
#pragma unroll 2
        for (int c0 = 0; c0 < NTILE; c0 += 8) {
            float p[8];
#pragma unroll
            for (int i = 0; i < 8; i++) p[i] = gp[(long)(c0 + i)*BB*FF];
            a0 += p[0]*fcs[c0+0]; a1 += p[1]*fcs[c0+1];
            a2 += p[2]*fcs[c0+2]; a3 += p[3]*fcs[c0+3];
            a0 += p[4]*fcs[c0+4]; a1 += p[5]*fcs[c0+5];
            a2 += p[6]*fcs[c0+6]; a3 += p[7]*fcs[c0+7];
        }
        x[HH + tid] = ((a0 + a1) + (a2 + a3)) * inv_den;
    } else {
        x[tid - 512] = g_embT[b*HH + tid - 512];
    }
    __syncthreads();

    // gi = x @ w_ih + b_ih : 32-wide load batches, 4 independent chains
    {
        const float* wp = w_ih + tid;
        float a0 = 0.f, a1 = 0.f, a2 = 0.f, a3 = 0.f;
        for (int k0 = 0; k0 < 3*HH; k0 += 32) {
            float w[32];
#pragma unroll
            for (int i = 0; i < 32; i++) w[i] = wp[(k0 + i)*(3*HH)];
#pragma unroll
            for (int i = 0; i < 32; i += 4) {
                a0 += x[k0+i]   * w[i];
                a1 += x[k0+i+1] * w[i+1];
                a2 += x[k0+i+2] * w[i+2];
                a3 += x[k0+i+3] * w[i+3];
            }
        }
        g[tid] = ((a0 + a1) + (a2 + a3)) + b_ih[tid];
    }
    __syncthreads();

    if (tid < HH) {
        const int j = tid;
        const float rg = sigmoidf_(g[j]        + b_hh[j]);
        const float zg = sigmoidf_(g[HH + j]   + b_hh[HH + j]);
        const float ng = tanhf   (g[2*HH + j]  + rg * b_hh[2*HH + j]);
        const float hv = (1.0f - zg) * ng;
        h[j] = hv;
        const int ho = BB*OUTD + b*HH + j;
        if (ho < out_size) out[ho] = hv;
    }
    __syncthreads();

    if (warp < OUTD) {
        float p = 0.0f;
#pragma unroll
        for (int i = 0; i < 8; i++) {
            int k = lane + i*32;
            p += h[k] * sW[k*OUTD + warp];
        }
#pragma unroll
        for (int o = 16; o; o >>= 1) p += __shfl_xor_sync(0xffffffffu, p, o);
        if (lane == 0) out[b*OUTD + warp] = p + out_b[warp];
    }
}

// ---------------- launch ----------------
extern "C" void kernel_launch(void* const* d_in, const int* in_sizes, int n_in,
                              void* d_out, int out_size)
{
    const int*   fc     = (const int*)  d_in[0];   // fut_ctxt (B,1)
    const int*   ft     = (const int*)  d_in[1];   // fut_temp (B,1)
    const float* E      = (const float*)d_in[2];   // encoder_outputs (B,S,2H)
    const float* emb_c  = (const float*)d_in[3];   // emb_ctxt (1000,H)
    const float* emb_t  = (const float*)d_in[4];   // emb_temp (1000,H)
    const float* attn_W = (const float*)d_in[5];   // (3H,H)
    const float* attn_b = (const float*)d_in[6];   // (H,)
    const float* v      = (const float*)d_in[7];   // (H,)
    const float* w_ih   = (const float*)d_in[8];   // (3H,3H)
    // d_in[9] = w_hh: unused since h0 == 0 (gh = b_hh exactly)
    const float* b_ih   = (const float*)d_in[10];  // (3H,)
    const float* b_hh   = (const float*)d_in[11];  // (3H,)
    const float* out_W  = (const float*)d_in[12];  // (H,OUT)
    const float* out_b  = (const float*)d_in[13];  // (OUT,)
    float* out = (float*)d_out;

    cudaFuncSetAttribute(scores_mma, cudaFuncAttributeMaxDynamicSharedMemorySize,
                         SMEM_SC);

    setup_prep<<<32 + 2*BB, 256>>>(fc, ft, emb_c, emb_t, attn_W, attn_b);
    scores_mma<<<dim3(NTILE, BB), 256, SMEM_SC>>>(E, v);
    gru_kernel<<<BB, 768>>>(w_ih, b_ih, b_hh, out_W, out_b, out, out_size);
}